// round 6
// baseline (speedup 1.0000x reference)
#include <cuda_runtime.h>
#include <cuda_bf16.h>
#include <math.h>
#include <stdint.h>

#define B_ 4
#define S_ 4096
#define D_ 512
#define F_ 2048
#define LN_EPS 1e-5f

#define BM 128
#define BN 256
#define BK 32
#define GT 256
#define KPAD_B 80                      // 32 bf16 padded to 40 -> 80 bytes/row (conflict-free ldmatrix)
#define A_TB (128 * KPAD_B)            // 10240 B
#define B_TB (256 * KPAD_B)            // 20480 B
#define OFF_AH 0
#define OFF_AL (A_TB)
#define OFF_BH (2 * A_TB)
#define OFF_BL (2 * A_TB + B_TB)
#define STAGE_B (2 * A_TB + 2 * B_TB)  // 61440
#define SMEM_DYN (2 * STAGE_B)         // 122880

// ---------------- scratch ----------------
__device__ __align__(128) float g_scores[(size_t)B_ * S_ * S_];
__device__ __align__(128) float g_t2[(size_t)B_ * S_ * D_];
__device__ __align__(128) float g_x1[(size_t)B_ * S_ * D_];
__device__ __align__(128) float g_x2[(size_t)B_ * S_ * D_];
__device__ double g_part[(size_t)B_ * 256 * 2];
__device__ float g_stats[B_ * 2];

__device__ __align__(128) __nv_bfloat16 g_xh[(size_t)B_*S_*D_],  g_xl[(size_t)B_*S_*D_];
__device__ __align__(128) __nv_bfloat16 g_eh[(size_t)B_*S_*D_],  g_el[(size_t)B_*S_*D_];
__device__ __align__(128) __nv_bfloat16 g_vth[(size_t)B_*D_*S_], g_vtl[(size_t)B_*D_*S_];
__device__ __align__(128) __nv_bfloat16 g_Ph[(size_t)B_*S_*S_],  g_Pl[(size_t)B_*S_*S_];
__device__ __align__(128) __nv_bfloat16 g_t1h[(size_t)B_*S_*D_], g_t1l[(size_t)B_*S_*D_];
__device__ __align__(128) __nv_bfloat16 g_x2h[(size_t)B_*S_*D_], g_x2l[(size_t)B_*S_*D_];
__device__ __align__(128) __nv_bfloat16 g_hh[(size_t)B_*S_*F_],  g_hl[(size_t)B_*S_*F_];
__device__ __align__(128) __nv_bfloat16 g_wo1h[D_*D_], g_wo1l[D_*D_];
__device__ __align__(128) __nv_bfloat16 g_wo2h[D_*D_], g_wo2l[D_*D_];
__device__ __align__(128) __nv_bfloat16 g_w1h[F_*D_],  g_w1l[F_*D_];
__device__ __align__(128) __nv_bfloat16 g_w2h[D_*F_],  g_w2l[D_*F_];

// ---------------- PTX helpers ----------------
__device__ __forceinline__ uint32_t smem_u32(const void* p) {
    return (uint32_t)__cvta_generic_to_shared(p);
}
__device__ __forceinline__ void cp16(uint32_t dst, const void* src) {
    asm volatile("cp.async.cg.shared.global [%0], [%1], 16;" :: "r"(dst), "l"(src));
}
__device__ __forceinline__ void cp_commit() {
    asm volatile("cp.async.commit_group;" ::: "memory");
}
__device__ __forceinline__ void ldsm4(uint32_t (&r)[4], uint32_t addr) {
    asm volatile("ldmatrix.sync.aligned.m8n8.x4.shared.b16 {%0,%1,%2,%3}, [%4];"
                 : "=r"(r[0]), "=r"(r[1]), "=r"(r[2]), "=r"(r[3]) : "r"(addr));
}
__device__ __forceinline__ void mma16816(float (&c)[4], const uint32_t (&a)[4],
                                         uint32_t b0, uint32_t b1) {
    asm volatile(
        "mma.sync.aligned.m16n8k16.row.col.f32.bf16.bf16.f32 "
        "{%0,%1,%2,%3}, {%4,%5,%6,%7}, {%8,%9}, {%0,%1,%2,%3};"
        : "+f"(c[0]), "+f"(c[1]), "+f"(c[2]), "+f"(c[3])
        : "r"(a[0]), "r"(a[1]), "r"(a[2]), "r"(a[3]), "r"(b0), "r"(b1));
}

// ---------------- split helpers ----------------
__device__ __forceinline__ void split2(float a, float b, uint32_t& h, uint32_t& l) {
    __nv_bfloat162 hh = __floats2bfloat162_rn(a, b);
    float ra = a - __low2float(hh);
    float rb = b - __high2float(hh);
    __nv_bfloat162 ll = __floats2bfloat162_rn(ra, rb);
    h = *reinterpret_cast<const uint32_t*>(&hh);
    l = *reinterpret_cast<const uint32_t*>(&ll);
}
__device__ __forceinline__ void split1(float a, __nv_bfloat16& h, __nv_bfloat16& l) {
    h = __float2bfloat16_rn(a);
    l = __float2bfloat16_rn(a - __bfloat162float(h));
}

// ---------------- stage loader ----------------
__device__ __forceinline__ void load_stage(uint32_t sb,
    const __nv_bfloat16* Ahp, const __nv_bfloat16* Alp,
    const __nv_bfloat16* Bhp, const __nv_bfloat16* Blp,
    int K, int kt, int tid)
{
    // A tiles: 128 rows x 4 16B-chunks = 512 cp16 each
#pragma unroll
    for (int j = 0; j < 2; j++) {
        const int idx = tid + j * 256;
        const int row = idx >> 2, c = idx & 3;
        cp16(sb + OFF_AH + row * KPAD_B + c * 16, Ahp + (size_t)row * K + kt + c * 8);
        cp16(sb + OFF_AL + row * KPAD_B + c * 16, Alp + (size_t)row * K + kt + c * 8);
    }
    // B tiles: 256 rows x 4 chunks = 1024 cp16 each
#pragma unroll
    for (int j = 0; j < 4; j++) {
        const int idx = tid + j * 256;
        const int row = idx >> 2, c = idx & 3;
        cp16(sb + OFF_BH + row * KPAD_B + c * 16, Bhp + (size_t)row * K + kt + c * 8);
        cp16(sb + OFF_BL + row * KPAD_B + c * 16, Blp + (size_t)row * K + kt + c * 8);
    }
}

// ---------------- tensor-core GEMM: D = alpha*A@B^T (+epilogue), bf16x3 split ----------------
// A: [M,K] hi/lo, B: [N,K] hi/lo (K-major). EPI: 0 scale, 1 +res, 2 relu(+bias), 3 +bias+res
// MODE: 0 none, 1 causal (skip blocks fully above diagonal), 2 clamp K to (by+1)*BM,
//       3 symmetric (compute blocks touching/below diagonal; mirror-write strict-lower elements)
// OUTB: 0 -> fp32 C; 1 -> bf16 hi/lo pair Ch/Cl
template<int EPI, int MODE, int OUTB>
__global__ __launch_bounds__(GT, 1)
void gemm_mma(const __nv_bfloat16* __restrict__ Ah, const __nv_bfloat16* __restrict__ Al,
              const __nv_bfloat16* __restrict__ Bh, const __nv_bfloat16* __restrict__ Bl,
              float* __restrict__ C, __nv_bfloat16* __restrict__ Ch, __nv_bfloat16* __restrict__ Cl,
              const float* __restrict__ Rres, const float* __restrict__ bias,
              int M, int N, int K, float alpha,
              long long strideA, long long strideB, long long strideC)
{
    const int bx = blockIdx.x, by = blockIdx.y, bz = blockIdx.z;
    if ((MODE == 1 || MODE == 3) && 2 * bx > by) return;

    extern __shared__ char smem[];
    const uint32_t sb0 = smem_u32(smem);

    const int tid = threadIdx.x;
    const int wid = tid >> 5, lane = tid & 31;
    const int warp_m = wid >> 2, warp_n = wid & 3;   // 2 x 4 warps; warp tile 64m x 64n
    const int lrow16 = lane & 15, lhi = lane >> 4;
    const int gr = lane >> 2, tg = lane & 3;

    const __nv_bfloat16* Ahp = Ah + (size_t)bz * strideA + (size_t)by * BM * K;
    const __nv_bfloat16* Alp = Al + (size_t)bz * strideA + (size_t)by * BM * K;
    const __nv_bfloat16* Bhp = Bh + (size_t)bz * strideB + (size_t)bx * BN * K;
    const __nv_bfloat16* Blp = Bl + (size_t)bz * strideB + (size_t)bx * BN * K;

    int kEnd = K;
    if (MODE == 2) { int ke = (by + 1) * BM; kEnd = ke < K ? ke : K; }
    const int nch = kEnd / BK;

    float acc[4][8][4];
#pragma unroll
    for (int mf = 0; mf < 4; mf++)
#pragma unroll
        for (int nf = 0; nf < 8; nf++)
#pragma unroll
            for (int r = 0; r < 4; r++) acc[mf][nf][r] = 0.f;

    const uint32_t a_lane = (uint32_t)((warp_m * 64 + lrow16) * KPAD_B + lhi * 16);
    const uint32_t b_lane = (uint32_t)((warp_n * 64 + lrow16) * KPAD_B + lhi * 16);

    load_stage(sb0, Ahp, Alp, Bhp, Blp, K, 0, tid);
    cp_commit();

    for (int c = 0; c < nch; ++c) {
        if (c + 1 < nch) {
            load_stage(sb0 + ((c + 1) & 1) * STAGE_B, Ahp, Alp, Bhp, Blp, K, (c + 1) * BK, tid);
            cp_commit();
            asm volatile("cp.async.wait_group 1;" ::: "memory");
        } else {
            asm volatile("cp.async.wait_group 0;" ::: "memory");
        }
        __syncthreads();

        const uint32_t buf = sb0 + (c & 1) * STAGE_B;
#pragma unroll
        for (int ks = 0; ks < 2; ks++) {
            uint32_t a_h[4][4], a_l[4][4], b_h[4][4], b_l[4][4];
#pragma unroll
            for (int mf = 0; mf < 4; mf++) {
                const uint32_t ad = buf + a_lane + (uint32_t)(mf * 16 * KPAD_B + ks * 32);
                ldsm4(a_h[mf], ad + OFF_AH);
                ldsm4(a_l[mf], ad + OFF_AL);
            }
#pragma unroll
            for (int hN = 0; hN < 4; hN++) {
                const uint32_t bd = buf + b_lane + (uint32_t)(hN * 16 * KPAD_B + ks * 32);
                ldsm4(b_h[hN], bd + OFF_BH);
                ldsm4(b_l[hN], bd + OFF_BL);
            }
#pragma unroll
            for (int mf = 0; mf < 4; mf++) {
#pragma unroll
                for (int nf = 0; nf < 8; nf++) {
                    const uint32_t bh0 = b_h[nf >> 1][nf & 1], bh1 = b_h[nf >> 1][2 + (nf & 1)];
                    const uint32_t bl0 = b_l[nf >> 1][nf & 1], bl1 = b_l[nf >> 1][2 + (nf & 1)];
                    mma16816(acc[mf][nf], a_h[mf], bh0, bh1);
                    mma16816(acc[mf][nf], a_h[mf], bl0, bl1);
                    mma16816(acc[mf][nf], a_l[mf], bh0, bh1);
                }
            }
        }
        __syncthreads();
    }

    // ---------------- epilogue ----------------
#pragma unroll
    for (int mf = 0; mf < 4; mf++) {
#pragma unroll
        for (int nf = 0; nf < 8; nf++) {
#pragma unroll
            for (int half = 0; half < 2; half++) {
                const int row = by * BM + warp_m * 64 + mf * 16 + gr + half * 8;
                const int col = bx * BN + warp_n * 64 + nf * 8 + tg * 2;
                float v0 = acc[mf][nf][half * 2 + 0] * alpha;
                float v1 = acc[mf][nf][half * 2 + 1] * alpha;
                if (EPI == 2 || EPI == 3) {
                    const float2 bb = *reinterpret_cast<const float2*>(&bias[col]);
                    v0 += bb.x; v1 += bb.y;
                }
                const size_t o = (size_t)bz * strideC + (size_t)row * N + col;
                if (EPI == 1 || EPI == 3) {
                    const float2 rr = *reinterpret_cast<const float2*>(&Rres[o]);
                    v0 += rr.x; v1 += rr.y;
                }
                if (EPI == 2) { v0 = fmaxf(v0, 0.f); v1 = fmaxf(v1, 0.f); }
                if (OUTB == 0) {
                    float2 st; st.x = v0; st.y = v1;
                    *reinterpret_cast<float2*>(&C[o]) = st;
                    if (MODE == 3) {   // mirror strict-lower elements to upper triangle
                        const size_t ob = (size_t)bz * strideC;
                        if (col < row)     C[ob + (size_t)col * N + row] = v0;
                        if (col + 1 < row) C[ob + (size_t)(col + 1) * N + row] = v1;
                    }
                } else {
                    uint32_t h, l;
                    split2(v0, v1, h, l);
                    *reinterpret_cast<uint32_t*>(&Ch[o]) = h;
                    *reinterpret_cast<uint32_t*>(&Cl[o]) = l;
                }
            }
        }
    }
}

// ---------------- softmax: fp32 scores -> bf16 hi/lo P ----------------
template<int CAUSAL>
__global__ void softmax_split_kernel(const float* __restrict__ Sc,
                                     __nv_bfloat16* __restrict__ Ph,
                                     __nv_bfloat16* __restrict__ Pl)
{
    const int T = 256, NC = S_ / T;
    const int row = blockIdx.x, b = blockIdx.y, t = threadIdx.x;
    const float* rp = Sc + ((size_t)b * S_ + row) * S_;
    __nv_bfloat16* hp = Ph + ((size_t)b * S_ + row) * S_;
    __nv_bfloat16* lp = Pl + ((size_t)b * S_ + row) * S_;
    const int limit = CAUSAL ? row + 1 : S_;
    // PV consumer only reads P columns < blockEnd (K clamped per 128-row band)
    const int blockEnd = CAUSAL ? (((row >> 7) + 1) << 7) : S_;

    float v[NC];
#pragma unroll
    for (int c = 0; c < NC; c++) {
        int j = t + c * T;
        v[c] = (j < limit) ? rp[j] : -INFINITY;
    }
    float m = -INFINITY;
#pragma unroll
    for (int c = 0; c < NC; c++) m = fmaxf(m, v[c]);
#pragma unroll
    for (int o = 16; o > 0; o >>= 1) m = fmaxf(m, __shfl_xor_sync(0xffffffffu, m, o));
    __shared__ float sred[8];
    if ((t & 31) == 0) sred[t >> 5] = m;
    __syncthreads();
    m = sred[0];
#pragma unroll
    for (int w = 1; w < 8; w++) m = fmaxf(m, sred[w]);
    __syncthreads();

    float s = 0.f;
#pragma unroll
    for (int c = 0; c < NC; c++) { float e = __expf(v[c] - m); v[c] = e; s += e; }
#pragma unroll
    for (int o = 16; o > 0; o >>= 1) s += __shfl_xor_sync(0xffffffffu, s, o);
    if ((t & 31) == 0) sred[t >> 5] = s;
    __syncthreads();
    s = 0.f;
#pragma unroll
    for (int w = 0; w < 8; w++) s += sred[w];
    const float inv = 1.f / s;
#pragma unroll
    for (int c = 0; c < NC; c++) {
        int j = t + c * T;
        if (j < blockEnd) {
            float p = v[c] * inv;
            __nv_bfloat16 h, l;
            split1(p, h, l);
            hp[j] = h; lp[j] = l;
        }
    }
}

// ---------------- elementwise fp32 -> bf16 hi/lo ----------------
__global__ void split_kernel(const float* __restrict__ X,
                             __nv_bfloat16* __restrict__ H, __nv_bfloat16* __restrict__ L)
{
    const size_t i = ((size_t)blockIdx.x * 256 + threadIdx.x) * 4;
    float4 v = *reinterpret_cast<const float4*>(X + i);
    uint32_t h0, l0, h1, l1;
    split2(v.x, v.y, h0, l0);
    split2(v.z, v.w, h1, l1);
    uint2 hv; hv.x = h0; hv.y = h1;
    uint2 lv; lv.x = l0; lv.y = l1;
    *reinterpret_cast<uint2*>(H + i) = hv;
    *reinterpret_cast<uint2*>(L + i) = lv;
}

// ---------------- transpose + split: fp32 [B,S,D] -> bf16 hi/lo [B,D,S] ----------------
__global__ void transpose_split_kernel(const float* __restrict__ X,
                                       __nv_bfloat16* __restrict__ Th,
                                       __nv_bfloat16* __restrict__ Tl)
{
    __shared__ float t[32][33];
    const int b = blockIdx.z;
    const int d0 = blockIdx.x * 32, s0 = blockIdx.y * 32;
    const float* Xp = X + (size_t)b * S_ * D_;
    for (int i = threadIdx.y; i < 32; i += 8)
        t[i][threadIdx.x] = Xp[(size_t)(s0 + i) * D_ + d0 + threadIdx.x];
    __syncthreads();
    for (int i = threadIdx.y; i < 32; i += 8) {
        float v = t[threadIdx.x][i];
        __nv_bfloat16 h, l;
        split1(v, h, l);
        size_t o = (size_t)b * D_ * S_ + (size_t)(d0 + i) * S_ + s0 + threadIdx.x;
        Th[o] = h; Tl[o] = l;
    }
}

// ---------------- joint LayerNorm over (S, D) per batch ----------------
__global__ void ln_reduce1_kernel(const float* __restrict__ X)
{
    const int b = blockIdx.y;
    const float* p = X + (size_t)b * S_ * D_;
    const size_t chunk = (size_t)S_ * D_ / 256;
    const size_t start = (size_t)blockIdx.x * chunk;
    double s = 0.0, s2 = 0.0;
    for (size_t i = start + threadIdx.x; i < start + chunk; i += 256) {
        float v = p[i];
        s += (double)v; s2 += (double)v * (double)v;
    }
    __shared__ double sh[256], sh2[256];
    sh[threadIdx.x] = s; sh2[threadIdx.x] = s2;
    __syncthreads();
    for (int o = 128; o > 0; o >>= 1) {
        if (threadIdx.x < o) {
            sh[threadIdx.x] += sh[threadIdx.x + o];
            sh2[threadIdx.x] += sh2[threadIdx.x + o];
        }
        __syncthreads();
    }
    if (threadIdx.x == 0) {
        g_part[((size_t)b * 256 + blockIdx.x) * 2]     = sh[0];
        g_part[((size_t)b * 256 + blockIdx.x) * 2 + 1] = sh2[0];
    }
}

__global__ void ln_reduce2_kernel()
{
    const int b = blockIdx.x;
    double s  = g_part[((size_t)b * 256 + threadIdx.x) * 2];
    double s2 = g_part[((size_t)b * 256 + threadIdx.x) * 2 + 1];
    __shared__ double sh[256], sh2[256];
    sh[threadIdx.x] = s; sh2[threadIdx.x] = s2;
    __syncthreads();
    for (int o = 128; o > 0; o >>= 1) {
        if (threadIdx.x < o) {
            sh[threadIdx.x] += sh[threadIdx.x + o];
            sh2[threadIdx.x] += sh2[threadIdx.x + o];
        }
        __syncthreads();
    }
    if (threadIdx.x == 0) {
        const double n = (double)S_ * (double)D_;
        double mu  = sh[0] / n;
        double var = sh2[0] / n - mu * mu;
        g_stats[b * 2]     = (float)mu;
        g_stats[b * 2 + 1] = (float)(1.0 / sqrt(var + (double)LN_EPS));
    }
}

__global__ void ln_apply_kernel(const float* __restrict__ X, const float* __restrict__ G,
                                const float* __restrict__ Be, float* __restrict__ Y)
{
    const size_t idx = (size_t)blockIdx.x * blockDim.x + threadIdx.x;
    const size_t sd = idx & ((size_t)S_ * D_ - 1);
    const int b = (int)(idx >> 21);
    const float mu = g_stats[b * 2], rs = g_stats[b * 2 + 1];
    Y[idx] = (X[idx] - mu) * rs * G[sd] + Be[sd];
}

__global__ void ln_apply_split_kernel(const float* __restrict__ X, const float* __restrict__ G,
                                      const float* __restrict__ Be, float* __restrict__ Y,
                                      __nv_bfloat16* __restrict__ Yh, __nv_bfloat16* __restrict__ Yl)
{
    const size_t idx = (size_t)blockIdx.x * blockDim.x + threadIdx.x;
    const size_t sd = idx & ((size_t)S_ * D_ - 1);
    const int b = (int)(idx >> 21);
    const float mu = g_stats[b * 2], rs = g_stats[b * 2 + 1];
    float y = (X[idx] - mu) * rs * G[sd] + Be[sd];
    Y[idx] = y;
    __nv_bfloat16 h, l;
    split1(y, h, l);
    Yh[idx] = h; Yl[idx] = l;
}

// ---------------- orchestration ----------------
extern "C" void kernel_launch(void* const* d_in, const int* in_sizes, int n_in,
                              void* d_out, int out_size)
{
    (void)in_sizes; (void)n_in; (void)out_size;
    const float* x    = (const float*)d_in[0];
    const float* enc  = (const float*)d_in[1];
    const float* Wo1  = (const float*)d_in[2];
    const float* Wo2  = (const float*)d_in[3];
    const float* ln1g = (const float*)d_in[4];
    const float* ln1b = (const float*)d_in[5];
    const float* ln2g = (const float*)d_in[6];
    const float* ln2b = (const float*)d_in[7];
    const float* W1   = (const float*)d_in[8];
    const float* b1   = (const float*)d_in[9];
    const float* W2   = (const float*)d_in[10];
    const float* b2   = (const float*)d_in[11];
    float* out = (float*)d_out;

    float *scores, *t2, *x1, *x2;
    cudaGetSymbolAddress((void**)&scores, g_scores);
    cudaGetSymbolAddress((void**)&t2, g_t2);
    cudaGetSymbolAddress((void**)&x1, g_x1);
    cudaGetSymbolAddress((void**)&x2, g_x2);
    __nv_bfloat16 *xh, *xl, *eh, *el, *vth, *vtl, *Ph, *Pl, *t1h, *t1l, *x2h, *x2l, *hh, *hl;
    __nv_bfloat16 *wo1h, *wo1l, *wo2h, *wo2l, *w1h, *w1l, *w2h, *w2l;
    cudaGetSymbolAddress((void**)&xh, g_xh);   cudaGetSymbolAddress((void**)&xl, g_xl);
    cudaGetSymbolAddress((void**)&eh, g_eh);   cudaGetSymbolAddress((void**)&el, g_el);
    cudaGetSymbolAddress((void**)&vth, g_vth); cudaGetSymbolAddress((void**)&vtl, g_vtl);
    cudaGetSymbolAddress((void**)&Ph, g_Ph);   cudaGetSymbolAddress((void**)&Pl, g_Pl);
    cudaGetSymbolAddress((void**)&t1h, g_t1h); cudaGetSymbolAddress((void**)&t1l, g_t1l);
    cudaGetSymbolAddress((void**)&x2h, g_x2h); cudaGetSymbolAddress((void**)&x2l, g_x2l);
    cudaGetSymbolAddress((void**)&hh, g_hh);   cudaGetSymbolAddress((void**)&hl, g_hl);
    cudaGetSymbolAddress((void**)&wo1h, g_wo1h); cudaGetSymbolAddress((void**)&wo1l, g_wo1l);
    cudaGetSymbolAddress((void**)&wo2h, g_wo2h); cudaGetSymbolAddress((void**)&wo2l, g_wo2l);
    cudaGetSymbolAddress((void**)&w1h, g_w1h);   cudaGetSymbolAddress((void**)&w1l, g_w1l);
    cudaGetSymbolAddress((void**)&w2h, g_w2h);   cudaGetSymbolAddress((void**)&w2l, g_w2l);

    cudaFuncSetAttribute(gemm_mma<0,1,0>, cudaFuncAttributeMaxDynamicSharedMemorySize, SMEM_DYN);
    cudaFuncSetAttribute(gemm_mma<0,3,0>, cudaFuncAttributeMaxDynamicSharedMemorySize, SMEM_DYN);
    cudaFuncSetAttribute(gemm_mma<0,2,1>, cudaFuncAttributeMaxDynamicSharedMemorySize, SMEM_DYN);
    cudaFuncSetAttribute(gemm_mma<0,0,1>, cudaFuncAttributeMaxDynamicSharedMemorySize, SMEM_DYN);
    cudaFuncSetAttribute(gemm_mma<1,0,0>, cudaFuncAttributeMaxDynamicSharedMemorySize, SMEM_DYN);
    cudaFuncSetAttribute(gemm_mma<2,0,1>, cudaFuncAttributeMaxDynamicSharedMemorySize, SMEM_DYN);
    cudaFuncSetAttribute(gemm_mma<3,0,0>, cudaFuncAttributeMaxDynamicSharedMemorySize, SMEM_DYN);

    const dim3 blk(GT);
    const float scale = 1.0f / sqrtf((float)D_);
    const long long sSS = (long long)S_ * S_;
    const long long sSD = (long long)S_ * D_;
    const long long sDS = (long long)D_ * S_;
    const int lnBlocks = (B_ * S_ * D_) / 256;
    const size_t nBSD = (size_t)B_ * S_ * D_;

    // ---- operand conversions ----
    split_kernel<<<(int)(nBSD / 1024), blk>>>(x, xh, xl);
    split_kernel<<<(int)(nBSD / 1024), blk>>>(enc, eh, el);
    split_kernel<<<D_ * D_ / 1024, blk>>>(Wo1, wo1h, wo1l);
    split_kernel<<<D_ * D_ / 1024, blk>>>(Wo2, wo2h, wo2l);
    split_kernel<<<F_ * D_ / 1024, blk>>>(W1, w1h, w1l);

    // ---- 1) causal self-attention + Wo1 + residual + ln1 ----
    gemm_mma<0,1,0><<<dim3(S_ / BN, S_ / BM, B_), blk, SMEM_DYN>>>(
        xh, xl, xh, xl, scores, nullptr, nullptr, nullptr, nullptr,
        S_, S_, D_, scale, sSD, sSD, sSS);

    split_kernel<<<D_ * F_ / 1024, blk>>>(W2, w2h, w2l);
    transpose_split_kernel<<<dim3(D_ / 32, S_ / 32, B_), dim3(32, 8)>>>(x, vth, vtl);

    softmax_split_kernel<1><<<dim3(S_, B_), blk>>>(scores, Ph, Pl);
    gemm_mma<0,2,1><<<dim3(D_ / BN, S_ / BM, B_), blk, SMEM_DYN>>>(
        Ph, Pl, vth, vtl, nullptr, t1h, t1l, nullptr, nullptr,
        S_, D_, S_, 1.f, sSS, sDS, sSD);
    gemm_mma<1,0,0><<<dim3(D_ / BN, (B_ * S_) / BM, 1), blk, SMEM_DYN>>>(
        t1h, t1l, wo1h, wo1l, t2, nullptr, nullptr, x, nullptr,
        B_ * S_, D_, D_, 1.f, 0, 0, 0);
    ln_reduce1_kernel<<<dim3(256, B_), blk>>>(t2);
    ln_reduce2_kernel<<<B_, blk>>>();
    ln_apply_kernel<<<lnBlocks, blk>>>(t2, ln1g, ln1b, x1);
    transpose_split_kernel<<<dim3(D_ / 32, S_ / 32, B_), dim3(32, 8)>>>(x1, vth, vtl);

    // ---- 2) cross attention (q=k=enc, v=x1): scores symmetric -> ~half the blocks ----
    gemm_mma<0,3,0><<<dim3(S_ / BN, S_ / BM, B_), blk, SMEM_DYN>>>(
        eh, el, eh, el, scores, nullptr, nullptr, nullptr, nullptr,
        S_, S_, D_, scale, sSD, sSD, sSS);
    softmax_split_kernel<0><<<dim3(S_, B_), blk>>>(scores, Ph, Pl);
    gemm_mma<0,0,1><<<dim3(D_ / BN, S_ / BM, B_), blk, SMEM_DYN>>>(
        Ph, Pl, vth, vtl, nullptr, t1h, t1l, nullptr, nullptr,
        S_, D_, S_, 1.f, sSS, sDS, sSD);
    gemm_mma<1,0,0><<<dim3(D_ / BN, (B_ * S_) / BM, 1), blk, SMEM_DYN>>>(
        t1h, t1l, wo2h, wo2l, t2, nullptr, nullptr, x1, nullptr,
        B_ * S_, D_, D_, 1.f, 0, 0, 0);
    ln_reduce1_kernel<<<dim3(256, B_), blk>>>(t2);
    ln_reduce2_kernel<<<B_, blk>>>();
    ln_apply_split_kernel<<<lnBlocks, blk>>>(t2, ln2g, ln2b, x2, x2h, x2l);

    // ---- 3) FFN + residual + ln2 (shared params) ----
    gemm_mma<2,0,1><<<dim3(F_ / BN, (B_ * S_) / BM, 1), blk, SMEM_DYN>>>(
        x2h, x2l, w1h, w1l, nullptr, hh, hl, nullptr, b1,
        B_ * S_, F_, D_, 1.f, 0, 0, 0);
    gemm_mma<3,0,0><<<dim3(D_ / BN, (B_ * S_) / BM, 1), blk, SMEM_DYN>>>(
        hh, hl, w2h, w2l, t2, nullptr, nullptr, x2, b2,
        B_ * S_, D_, F_, 1.f, 0, 0, 0);
    ln_reduce1_kernel<<<dim3(256, B_), blk>>>(t2);
    ln_reduce2_kernel<<<B_, blk>>>();
    ln_apply_kernel<<<lnBlocks, blk>>>(t2, ln2g, ln2b, out);
}

// round 7
// speedup vs baseline: 1.3488x; 1.3488x over previous
#include <cuda_runtime.h>
#include <cuda_fp16.h>
#include <math.h>
#include <stdint.h>

#define B_ 4
#define S_ 4096
#define D_ 512
#define F_ 2048
#define LN_EPS 1e-5f

#define BM 128
#define BN 128
#define BK 32
#define GT 256
#define KPAD_B 80                      // 32 fp16 padded to 40 -> 80 bytes/row
#define TILE_B (128 * KPAD_B)          // 10240 B
#define OFF_AH 0
#define OFF_AL (TILE_B)
#define OFF_BH (2 * TILE_B)
#define STAGE_B (3 * TILE_B)           // 30720
#define SMEM_DYN (2 * STAGE_B)         // 61440

// ---------------- scratch ----------------
__device__ __align__(128) float g_scores[(size_t)B_ * S_ * S_];
__device__ __align__(128) float g_t2[(size_t)B_ * S_ * D_];
__device__ __align__(128) float g_x1[(size_t)B_ * S_ * D_];
__device__ __align__(128) float g_x2[(size_t)B_ * S_ * D_];
__device__ double g_part[(size_t)B_ * 256 * 2];
__device__ float g_stats[B_ * 2];

__device__ __align__(128) __half g_xh[(size_t)B_*S_*D_],  g_xl[(size_t)B_*S_*D_];
__device__ __align__(128) __half g_eh[(size_t)B_*S_*D_],  g_el[(size_t)B_*S_*D_];
__device__ __align__(128) __half g_vth[(size_t)B_*D_*S_];
__device__ __align__(128) __half g_Ph[(size_t)B_*S_*S_],  g_Pl[(size_t)B_*S_*S_];
__device__ __align__(128) __half g_t1h[(size_t)B_*S_*D_], g_t1l[(size_t)B_*S_*D_];
__device__ __align__(128) __half g_x2h[(size_t)B_*S_*D_], g_x2l[(size_t)B_*S_*D_];
__device__ __align__(128) __half g_hh[(size_t)B_*S_*F_],  g_hl[(size_t)B_*S_*F_];
__device__ __align__(128) __half g_wo1h[D_*D_], g_wo2h[D_*D_];
__device__ __align__(128) __half g_w1h[F_*D_],  g_w2h[D_*F_];

// ---------------- PTX helpers ----------------
__device__ __forceinline__ uint32_t smem_u32(const void* p) {
    return (uint32_t)__cvta_generic_to_shared(p);
}
__device__ __forceinline__ void cp16(uint32_t dst, const void* src) {
    asm volatile("cp.async.cg.shared.global [%0], [%1], 16;" :: "r"(dst), "l"(src));
}
__device__ __forceinline__ void cp_commit() {
    asm volatile("cp.async.commit_group;" ::: "memory");
}
__device__ __forceinline__ void ldsm4(uint32_t (&r)[4], uint32_t addr) {
    asm volatile("ldmatrix.sync.aligned.m8n8.x4.shared.b16 {%0,%1,%2,%3}, [%4];"
                 : "=r"(r[0]), "=r"(r[1]), "=r"(r[2]), "=r"(r[3]) : "r"(addr));
}
__device__ __forceinline__ void mma16816(float (&c)[4], const uint32_t (&a)[4],
                                         uint32_t b0, uint32_t b1) {
    asm volatile(
        "mma.sync.aligned.m16n8k16.row.col.f32.f16.f16.f32 "
        "{%0,%1,%2,%3}, {%4,%5,%6,%7}, {%8,%9}, {%0,%1,%2,%3};"
        : "+f"(c[0]), "+f"(c[1]), "+f"(c[2]), "+f"(c[3])
        : "r"(a[0]), "r"(a[1]), "r"(a[2]), "r"(a[3]), "r"(b0), "r"(b1));
}

// ---------------- split helpers (fp16 hi/lo) ----------------
__device__ __forceinline__ void split2h(float a, float b, uint32_t& h, uint32_t& l) {
    __half ha = __float2half_rn(a), hb = __float2half_rn(b);
    __half la = __float2half_rn(a - __half2float(ha));
    __half lb = __float2half_rn(b - __half2float(hb));
    __half2 hh = __halves2half2(ha, hb), ll = __halves2half2(la, lb);
    h = *reinterpret_cast<const uint32_t*>(&hh);
    l = *reinterpret_cast<const uint32_t*>(&ll);
}
__device__ __forceinline__ void split1h(float a, __half& h, __half& l) {
    h = __float2half_rn(a);
    l = __float2half_rn(a - __half2float(h));
}

// ---------------- stage loader: Ah, Al, Bh -> padded smem ----------------
__device__ __forceinline__ void load_stage(uint32_t sb,
    const __half* Ahp, const __half* Alp, const __half* Bhp,
    int K, int kt, int tid)
{
#pragma unroll
    for (int j = 0; j < 2; j++) {
        const int idx = tid + j * 256;            // 0..511
        const int row = idx >> 2, c = idx & 3;
        const size_t go = (size_t)row * K + kt + c * 8;
        const uint32_t so = row * KPAD_B + c * 16;
        cp16(sb + OFF_AH + so, Ahp + go);
        cp16(sb + OFF_AL + so, Alp + go);
        cp16(sb + OFF_BH + so, Bhp + go);
    }
}

// ---------------- tensor-core GEMM: D = alpha*(Ah+Al)@Bh^T (+epilogue), fp16x2 ----------------
// EPI: 0 scale, 1 +res, 2 relu(+bias), 3 +bias+res
// MODE: 0 none, 1 causal (skip blocks above diagonal), 2 clamp K to (by+1)*BM,
//       3 symmetric (bx<=by only; mirror strict-lower elements)
// OUTB: 0 -> fp32 C; 1 -> fp16 hi/lo pair Ch/Cl
template<int EPI, int MODE, int OUTB>
__global__ __launch_bounds__(GT, 1)
void gemm_mma(const __half* __restrict__ Ah, const __half* __restrict__ Al,
              const __half* __restrict__ Bh,
              float* __restrict__ C, __half* __restrict__ Ch, __half* __restrict__ Cl,
              const float* __restrict__ Rres, const float* __restrict__ bias,
              int M, int N, int K, float alpha,
              long long strideA, long long strideB, long long strideC)
{
    const int bx = blockIdx.x, by = blockIdx.y, bz = blockIdx.z;
    if ((MODE == 1 || MODE == 3) && bx > by) return;

    extern __shared__ char smem[];
    const uint32_t sb0 = smem_u32(smem);

    const int tid = threadIdx.x;
    const int wid = tid >> 5, lane = tid & 31;
    const int warp_m = wid >> 2, warp_n = wid & 3;   // 2 x 4 warps; warp tile 64m x 32n
    const int lrow16 = lane & 15, lhi = lane >> 4;
    const int gr = lane >> 2, tg = lane & 3;

    const __half* Ahp = Ah + (size_t)bz * strideA + (size_t)by * BM * K;
    const __half* Alp = Al + (size_t)bz * strideA + (size_t)by * BM * K;
    const __half* Bhp = Bh + (size_t)bz * strideB + (size_t)bx * BN * K;

    int kEnd = K;
    if (MODE == 2) { int ke = (by + 1) * BM; kEnd = ke < K ? ke : K; }
    const int nch = kEnd / BK;

    float acc[4][4][4];
#pragma unroll
    for (int mf = 0; mf < 4; mf++)
#pragma unroll
        for (int nf = 0; nf < 4; nf++)
#pragma unroll
            for (int r = 0; r < 4; r++) acc[mf][nf][r] = 0.f;

    const uint32_t a_lane = (uint32_t)((warp_m * 64 + lrow16) * KPAD_B + lhi * 16);
    const uint32_t b_lane = (uint32_t)((warp_n * 32 + lrow16) * KPAD_B + lhi * 16);

    load_stage(sb0, Ahp, Alp, Bhp, K, 0, tid);
    cp_commit();

    for (int c = 0; c < nch; ++c) {
        if (c + 1 < nch) {
            load_stage(sb0 + ((c + 1) & 1) * STAGE_B, Ahp, Alp, Bhp, K, (c + 1) * BK, tid);
            cp_commit();
            asm volatile("cp.async.wait_group 1;" ::: "memory");
        } else {
            asm volatile("cp.async.wait_group 0;" ::: "memory");
        }
        __syncthreads();

        const uint32_t buf = sb0 + (c & 1) * STAGE_B;
#pragma unroll
        for (int ks = 0; ks < 2; ks++) {
            uint32_t a_h[4][4], a_l[4][4], b_h[2][4];
#pragma unroll
            for (int mf = 0; mf < 4; mf++) {
                const uint32_t ad = buf + a_lane + (uint32_t)(mf * 16 * KPAD_B + ks * 32);
                ldsm4(a_h[mf], ad + OFF_AH);
                ldsm4(a_l[mf], ad + OFF_AL);
            }
#pragma unroll
            for (int hN = 0; hN < 2; hN++) {
                const uint32_t bd = buf + b_lane + (uint32_t)(hN * 16 * KPAD_B + ks * 32);
                ldsm4(b_h[hN], bd + OFF_BH);
            }
#pragma unroll
            for (int mf = 0; mf < 4; mf++) {
#pragma unroll
                for (int nf = 0; nf < 4; nf++) {
                    const uint32_t bh0 = b_h[nf >> 1][nf & 1], bh1 = b_h[nf >> 1][2 + (nf & 1)];
                    mma16816(acc[mf][nf], a_h[mf], bh0, bh1);
                    mma16816(acc[mf][nf], a_l[mf], bh0, bh1);
                }
            }
        }
        __syncthreads();
    }

    // ---------------- epilogue ----------------
#pragma unroll
    for (int mf = 0; mf < 4; mf++) {
#pragma unroll
        for (int nf = 0; nf < 4; nf++) {
#pragma unroll
            for (int half = 0; half < 2; half++) {
                const int row = by * BM + warp_m * 64 + mf * 16 + gr + half * 8;
                const int col = bx * BN + warp_n * 32 + nf * 8 + tg * 2;
                float v0 = acc[mf][nf][half * 2 + 0] * alpha;
                float v1 = acc[mf][nf][half * 2 + 1] * alpha;
                if (EPI == 2 || EPI == 3) {
                    const float2 bb = *reinterpret_cast<const float2*>(&bias[col]);
                    v0 += bb.x; v1 += bb.y;
                }
                const size_t o = (size_t)bz * strideC + (size_t)row * N + col;
                if (EPI == 1 || EPI == 3) {
                    const float2 rr = *reinterpret_cast<const float2*>(&Rres[o]);
                    v0 += rr.x; v1 += rr.y;
                }
                if (EPI == 2) { v0 = fmaxf(v0, 0.f); v1 = fmaxf(v1, 0.f); }
                if (OUTB == 0) {
                    float2 st; st.x = v0; st.y = v1;
                    *reinterpret_cast<float2*>(&C[o]) = st;
                    if (MODE == 3) {   // mirror strict-lower elements
                        const size_t ob = (size_t)bz * strideC;
                        if (col < row)     C[ob + (size_t)col * N + row] = v0;
                        if (col + 1 < row) C[ob + (size_t)(col + 1) * N + row] = v1;
                    }
                } else {
                    uint32_t h, l;
                    split2h(v0, v1, h, l);
                    *reinterpret_cast<uint32_t*>(&Ch[o]) = h;
                    *reinterpret_cast<uint32_t*>(&Cl[o]) = l;
                }
            }
        }
    }
}

// ---------------- softmax: fp32 scores -> fp16 hi/lo P ----------------
template<int CAUSAL>
__global__ void softmax_split_kernel(const float* __restrict__ Sc,
                                     __half* __restrict__ Ph, __half* __restrict__ Pl)
{
    const int T = 256, NC = S_ / T;
    const int row = blockIdx.x, b = blockIdx.y, t = threadIdx.x;
    const float* rp = Sc + ((size_t)b * S_ + row) * S_;
    __half* hp = Ph + ((size_t)b * S_ + row) * S_;
    __half* lp = Pl + ((size_t)b * S_ + row) * S_;
    const int limit = CAUSAL ? row + 1 : S_;
    const int blockEnd = CAUSAL ? (((row >> 7) + 1) << 7) : S_;

    float v[NC];
#pragma unroll
    for (int c = 0; c < NC; c++) {
        int j = t + c * T;
        v[c] = (j < limit) ? rp[j] : -INFINITY;
    }
    float m = -INFINITY;
#pragma unroll
    for (int c = 0; c < NC; c++) m = fmaxf(m, v[c]);
#pragma unroll
    for (int o = 16; o > 0; o >>= 1) m = fmaxf(m, __shfl_xor_sync(0xffffffffu, m, o));
    __shared__ float sred[8];
    if ((t & 31) == 0) sred[t >> 5] = m;
    __syncthreads();
    m = sred[0];
#pragma unroll
    for (int w = 1; w < 8; w++) m = fmaxf(m, sred[w]);
    __syncthreads();

    float s = 0.f;
#pragma unroll
    for (int c = 0; c < NC; c++) { float e = __expf(v[c] - m); v[c] = e; s += e; }
#pragma unroll
    for (int o = 16; o > 0; o >>= 1) s += __shfl_xor_sync(0xffffffffu, s, o);
    if ((t & 31) == 0) sred[t >> 5] = s;
    __syncthreads();
    s = 0.f;
#pragma unroll
    for (int w = 0; w < 8; w++) s += sred[w];
    const float inv = 1.f / s;
#pragma unroll
    for (int c = 0; c < NC; c++) {
        int j = t + c * T;
        if (j < blockEnd) {
            float p = v[c] * inv;
            __half h, l;
            split1h(p, h, l);
            hp[j] = h; lp[j] = l;
        }
    }
}

// ---------------- elementwise fp32 -> fp16 hi/lo ----------------
__global__ void split_kernel(const float* __restrict__ X,
                             __half* __restrict__ H, __half* __restrict__ L)
{
    const size_t i = ((size_t)blockIdx.x * 256 + threadIdx.x) * 4;
    float4 v = *reinterpret_cast<const float4*>(X + i);
    uint32_t h0, l0, h1, l1;
    split2h(v.x, v.y, h0, l0);
    split2h(v.z, v.w, h1, l1);
    uint2 hv; hv.x = h0; hv.y = h1;
    uint2 lv; lv.x = l0; lv.y = l1;
    *reinterpret_cast<uint2*>(H + i) = hv;
    *reinterpret_cast<uint2*>(L + i) = lv;
}

// ---------------- elementwise fp32 -> fp16 (hi only, B-side operands) ----------------
__global__ void half_kernel(const float* __restrict__ X, __half* __restrict__ H)
{
    const size_t i = ((size_t)blockIdx.x * 256 + threadIdx.x) * 4;
    float4 v = *reinterpret_cast<const float4*>(X + i);
    __half2 a = __floats2half2_rn(v.x, v.y);
    __half2 b = __floats2half2_rn(v.z, v.w);
    uint2 hv;
    hv.x = *reinterpret_cast<const uint32_t*>(&a);
    hv.y = *reinterpret_cast<const uint32_t*>(&b);
    *reinterpret_cast<uint2*>(H + i) = hv;
}

// ---------------- transpose + to-fp16: fp32 [B,S,D] -> fp16 [B,D,S] ----------------
__global__ void transpose_half_kernel(const float* __restrict__ X, __half* __restrict__ Th)
{
    __shared__ float t[32][33];
    const int b = blockIdx.z;
    const int d0 = blockIdx.x * 32, s0 = blockIdx.y * 32;
    const float* Xp = X + (size_t)b * S_ * D_;
    for (int i = threadIdx.y; i < 32; i += 8)
        t[i][threadIdx.x] = Xp[(size_t)(s0 + i) * D_ + d0 + threadIdx.x];
    __syncthreads();
    for (int i = threadIdx.y; i < 32; i += 8) {
        size_t o = (size_t)b * D_ * S_ + (size_t)(d0 + i) * S_ + s0 + threadIdx.x;
        Th[o] = __float2half_rn(t[threadIdx.x][i]);
    }
}

// ---------------- joint LayerNorm over (S, D) per batch ----------------
__global__ void ln_reduce1_kernel(const float* __restrict__ X)
{
    const int b = blockIdx.y;
    const float* p = X + (size_t)b * S_ * D_;
    const size_t chunk = (size_t)S_ * D_ / 256;
    const size_t start = (size_t)blockIdx.x * chunk;
    double s = 0.0, s2 = 0.0;
    for (size_t i = start + threadIdx.x; i < start + chunk; i += 256) {
        float v = p[i];
        s += (double)v; s2 += (double)v * (double)v;
    }
    __shared__ double sh[256], sh2[256];
    sh[threadIdx.x] = s; sh2[threadIdx.x] = s2;
    __syncthreads();
    for (int o = 128; o > 0; o >>= 1) {
        if (threadIdx.x < o) {
            sh[threadIdx.x] += sh[threadIdx.x + o];
            sh2[threadIdx.x] += sh2[threadIdx.x + o];
        }
        __syncthreads();
    }
    if (threadIdx.x == 0) {
        g_part[((size_t)b * 256 + blockIdx.x) * 2]     = sh[0];
        g_part[((size_t)b * 256 + blockIdx.x) * 2 + 1] = sh2[0];
    }
}

__global__ void ln_reduce2_kernel()
{
    const int b = blockIdx.x;
    double s  = g_part[((size_t)b * 256 + threadIdx.x) * 2];
    double s2 = g_part[((size_t)b * 256 + threadIdx.x) * 2 + 1];
    __shared__ double sh[256], sh2[256];
    sh[threadIdx.x] = s; sh2[threadIdx.x] = s2;
    __syncthreads();
    for (int o = 128; o > 0; o >>= 1) {
        if (threadIdx.x < o) {
            sh[threadIdx.x] += sh[threadIdx.x + o];
            sh2[threadIdx.x] += sh2[threadIdx.x + o];
        }
        __syncthreads();
    }
    if (threadIdx.x == 0) {
        const double n = (double)S_ * (double)D_;
        double mu  = sh[0] / n;
        double var = sh2[0] / n - mu * mu;
        g_stats[b * 2]     = (float)mu;
        g_stats[b * 2 + 1] = (float)(1.0 / sqrt(var + (double)LN_EPS));
    }
}

__global__ void ln_apply_kernel(const float* __restrict__ X, const float* __restrict__ G,
                                const float* __restrict__ Be, float* __restrict__ Y)
{
    const size_t idx = (size_t)blockIdx.x * blockDim.x + threadIdx.x;
    const size_t sd = idx & ((size_t)S_ * D_ - 1);
    const int b = (int)(idx >> 21);
    const float mu = g_stats[b * 2], rs = g_stats[b * 2 + 1];
    Y[idx] = (X[idx] - mu) * rs * G[sd] + Be[sd];
}

__global__ void ln_apply_split_kernel(const float* __restrict__ X, const float* __restrict__ G,
                                      const float* __restrict__ Be, float* __restrict__ Y,
                                      __half* __restrict__ Yh, __half* __restrict__ Yl)
{
    const size_t idx = (size_t)blockIdx.x * blockDim.x + threadIdx.x;
    const size_t sd = idx & ((size_t)S_ * D_ - 1);
    const int b = (int)(idx >> 21);
    const float mu = g_stats[b * 2], rs = g_stats[b * 2 + 1];
    float y = (X[idx] - mu) * rs * G[sd] + Be[sd];
    Y[idx] = y;
    __half h, l;
    split1h(y, h, l);
    Yh[idx] = h; Yl[idx] = l;
}

// ---------------- orchestration ----------------
extern "C" void kernel_launch(void* const* d_in, const int* in_sizes, int n_in,
                              void* d_out, int out_size)
{
    (void)in_sizes; (void)n_in; (void)out_size;
    const float* x    = (const float*)d_in[0];
    const float* enc  = (const float*)d_in[1];
    const float* Wo1  = (const float*)d_in[2];
    const float* Wo2  = (const float*)d_in[3];
    const float* ln1g = (const float*)d_in[4];
    const float* ln1b = (const float*)d_in[5];
    const float* ln2g = (const float*)d_in[6];
    const float* ln2b = (const float*)d_in[7];
    const float* W1   = (const float*)d_in[8];
    const float* b1   = (const float*)d_in[9];
    const float* W2   = (const float*)d_in[10];
    const float* b2   = (const float*)d_in[11];
    float* out = (float*)d_out;

    float *scores, *t2, *x1, *x2;
    cudaGetSymbolAddress((void**)&scores, g_scores);
    cudaGetSymbolAddress((void**)&t2, g_t2);
    cudaGetSymbolAddress((void**)&x1, g_x1);
    cudaGetSymbolAddress((void**)&x2, g_x2);
    __half *xh, *xl, *eh, *el, *vth, *Ph, *Pl, *t1h, *t1l, *x2h, *x2l, *hh, *hl;
    __half *wo1h, *wo2h, *w1h, *w2h;
    cudaGetSymbolAddress((void**)&xh, g_xh);   cudaGetSymbolAddress((void**)&xl, g_xl);
    cudaGetSymbolAddress((void**)&eh, g_eh);   cudaGetSymbolAddress((void**)&el, g_el);
    cudaGetSymbolAddress((void**)&vth, g_vth);
    cudaGetSymbolAddress((void**)&Ph, g_Ph);   cudaGetSymbolAddress((void**)&Pl, g_Pl);
    cudaGetSymbolAddress((void**)&t1h, g_t1h); cudaGetSymbolAddress((void**)&t1l, g_t1l);
    cudaGetSymbolAddress((void**)&x2h, g_x2h); cudaGetSymbolAddress((void**)&x2l, g_x2l);
    cudaGetSymbolAddress((void**)&hh, g_hh);   cudaGetSymbolAddress((void**)&hl, g_hl);
    cudaGetSymbolAddress((void**)&wo1h, g_wo1h); cudaGetSymbolAddress((void**)&wo2h, g_wo2h);
    cudaGetSymbolAddress((void**)&w1h, g_w1h);   cudaGetSymbolAddress((void**)&w2h, g_w2h);

    cudaFuncSetAttribute(gemm_mma<0,1,0>, cudaFuncAttributeMaxDynamicSharedMemorySize, SMEM_DYN);
    cudaFuncSetAttribute(gemm_mma<0,3,0>, cudaFuncAttributeMaxDynamicSharedMemorySize, SMEM_DYN);
    cudaFuncSetAttribute(gemm_mma<0,2,1>, cudaFuncAttributeMaxDynamicSharedMemorySize, SMEM_DYN);
    cudaFuncSetAttribute(gemm_mma<0,0,1>, cudaFuncAttributeMaxDynamicSharedMemorySize, SMEM_DYN);
    cudaFuncSetAttribute(gemm_mma<1,0,0>, cudaFuncAttributeMaxDynamicSharedMemorySize, SMEM_DYN);
    cudaFuncSetAttribute(gemm_mma<2,0,1>, cudaFuncAttributeMaxDynamicSharedMemorySize, SMEM_DYN);
    cudaFuncSetAttribute(gemm_mma<3,0,0>, cudaFuncAttributeMaxDynamicSharedMemorySize, SMEM_DYN);

    const dim3 blk(GT);
    const float scale = 1.0f / sqrtf((float)D_);
    const long long sSS = (long long)S_ * S_;
    const long long sSD = (long long)S_ * D_;
    const long long sDS = (long long)D_ * S_;
    const int lnBlocks = (B_ * S_ * D_) / 256;
    const size_t nBSD = (size_t)B_ * S_ * D_;

    // ---- operand conversions ----
    split_kernel<<<(int)(nBSD / 1024), blk>>>(x, xh, xl);
    split_kernel<<<(int)(nBSD / 1024), blk>>>(enc, eh, el);
    half_kernel<<<D_ * D_ / 1024, blk>>>(Wo1, wo1h);
    half_kernel<<<D_ * D_ / 1024, blk>>>(Wo2, wo2h);
    half_kernel<<<F_ * D_ / 1024, blk>>>(W1, w1h);

    // ---- 1) causal self-attention + Wo1 + residual + ln1 ----
    gemm_mma<0,1,0><<<dim3(S_ / BN, S_ / BM, B_), blk, SMEM_DYN>>>(
        xh, xl, xh, scores, nullptr, nullptr, nullptr, nullptr,
        S_, S_, D_, scale, sSD, sSD, sSS);

    half_kernel<<<D_ * F_ / 1024, blk>>>(W2, w2h);
    transpose_half_kernel<<<dim3(D_ / 32, S_ / 32, B_), dim3(32, 8)>>>(x, vth);

    softmax_split_kernel<1><<<dim3(S_, B_), blk>>>(scores, Ph, Pl);
    gemm_mma<0,2,1><<<dim3(D_ / BN, S_ / BM, B_), blk, SMEM_DYN>>>(
        Ph, Pl, vth, nullptr, t1h, t1l, nullptr, nullptr,
        S_, D_, S_, 1.f, sSS, sDS, sSD);
    gemm_mma<1,0,0><<<dim3(D_ / BN, (B_ * S_) / BM, 1), blk, SMEM_DYN>>>(
        t1h, t1l, wo1h, t2, nullptr, nullptr, x, nullptr,
        B_ * S_, D_, D_, 1.f, 0, 0, 0);
    ln_reduce1_kernel<<<dim3(256, B_), blk>>>(t2);
    ln_reduce2_kernel<<<B_, blk>>>();
    ln_apply_kernel<<<lnBlocks, blk>>>(t2, ln1g, ln1b, x1);
    transpose_half_kernel<<<dim3(D_ / 32, S_ / 32, B_), dim3(32, 8)>>>(x1, vth);

    // ---- 2) cross attention (q=k=enc, v=x1): scores symmetric -> half the blocks ----
    gemm_mma<0,3,0><<<dim3(S_ / BN, S_ / BM, B_), blk, SMEM_DYN>>>(
        eh, el, eh, scores, nullptr, nullptr, nullptr, nullptr,
        S_, S_, D_, scale, sSD, sSD, sSS);
    softmax_split_kernel<0><<<dim3(S_, B_), blk>>>(scores, Ph, Pl);
    gemm_mma<0,0,1><<<dim3(D_ / BN, S_ / BM, B_), blk, SMEM_DYN>>>(
        Ph, Pl, vth, nullptr, t1h, t1l, nullptr, nullptr,
        S_, D_, S_, 1.f, sSS, sDS, sSD);
    gemm_mma<1,0,0><<<dim3(D_ / BN, (B_ * S_) / BM, 1), blk, SMEM_DYN>>>(
        t1h, t1l, wo2h, t2, nullptr, nullptr, x1, nullptr,
        B_ * S_, D_, D_, 1.f, 0, 0, 0);
    ln_reduce1_kernel<<<dim3(256, B_), blk>>>(t2);
    ln_reduce2_kernel<<<B_, blk>>>();
    ln_apply_split_kernel<<<lnBlocks, blk>>>(t2, ln2g, ln2b, x2, x2h, x2l);

    // ---- 3) FFN + residual + ln2 (shared params) ----
    gemm_mma<2,0,1><<<dim3(F_ / BN, (B_ * S_) / BM, 1), blk, SMEM_DYN>>>(
        x2h, x2l, w1h, nullptr, hh, hl, nullptr, b1,
        B_ * S_, F_, D_, 1.f, 0, 0, 0);
    gemm_mma<3,0,0><<<dim3(D_ / BN, (B_ * S_) / BM, 1), blk, SMEM_DYN>>>(
        hh, hl, w2h, t2, nullptr, nullptr, x2, b2,
        B_ * S_, D_, F_, 1.f, 0, 0, 0);
    ln_reduce1_kernel<<<dim3(256, B_), blk>>>(t2);
    ln_reduce2_kernel<<<B_, blk>>>();
    ln_apply_kernel<<<lnBlocks, blk>>>(t2, ln2g, ln2b, out);
}

// round 8
// speedup vs baseline: 2.1521x; 1.5955x over previous
#include <cuda_runtime.h>
#include <cuda_fp16.h>
#include <math.h>
#include <stdint.h>

#define B_ 4
#define S_ 4096
#define D_ 512
#define F_ 2048
#define LN_EPS 1e-5f

#define BM 128
#define BN 128
#define BK 32
#define GT 256
#define KPAD_B 80                      // 32 fp16 padded to 40 -> 80 bytes/row
#define TILE_B (128 * KPAD_B)          // 10240 B
#define OFF_A 0
#define OFF_B (TILE_B)
#define STAGE_B (2 * TILE_B)           // 20480
#define SMEM_DYN (2 * STAGE_B)         // 40960

// ---------------- scratch ----------------
__device__ __align__(128) float g_scores[(size_t)B_ * S_ * S_];
__device__ __align__(128) float g_t2[(size_t)B_ * S_ * D_];
__device__ __align__(128) float g_x1[(size_t)B_ * S_ * D_];
__device__ __align__(128) float g_x2[(size_t)B_ * S_ * D_];
__device__ double g_part[(size_t)B_ * 256 * 2];
__device__ float g_stats[B_ * 2];

__device__ __align__(128) __half g_xh[(size_t)B_*S_*D_];
__device__ __align__(128) __half g_eh[(size_t)B_*S_*D_];
__device__ __align__(128) __half g_vth[(size_t)B_*D_*S_];
__device__ __align__(128) __half g_Ph[(size_t)B_*S_*S_];
__device__ __align__(128) __half g_t1h[(size_t)B_*S_*D_];
__device__ __align__(128) __half g_x2h[(size_t)B_*S_*D_];
__device__ __align__(128) __half g_hh[(size_t)B_*S_*F_];
__device__ __align__(128) __half g_wo1h[D_*D_], g_wo2h[D_*D_];
__device__ __align__(128) __half g_w1h[F_*D_],  g_w2h[D_*F_];

// ---------------- PTX helpers ----------------
__device__ __forceinline__ uint32_t smem_u32(const void* p) {
    return (uint32_t)__cvta_generic_to_shared(p);
}
__device__ __forceinline__ void cp16(uint32_t dst, const void* src) {
    asm volatile("cp.async.cg.shared.global [%0], [%1], 16;" :: "r"(dst), "l"(src));
}
__device__ __forceinline__ void cp_commit() {
    asm volatile("cp.async.commit_group;" ::: "memory");
}
__device__ __forceinline__ void ldsm4(uint32_t (&r)[4], uint32_t addr) {
    asm volatile("ldmatrix.sync.aligned.m8n8.x4.shared.b16 {%0,%1,%2,%3}, [%4];"
                 : "=r"(r[0]), "=r"(r[1]), "=r"(r[2]), "=r"(r[3]) : "r"(addr));
}
__device__ __forceinline__ void mma16816(float (&c)[4], const uint32_t (&a)[4],
                                         uint32_t b0, uint32_t b1) {
    asm volatile(
        "mma.sync.aligned.m16n8k16.row.col.f32.f16.f16.f32 "
        "{%0,%1,%2,%3}, {%4,%5,%6,%7}, {%8,%9}, {%0,%1,%2,%3};"
        : "+f"(c[0]), "+f"(c[1]), "+f"(c[2]), "+f"(c[3])
        : "r"(a[0]), "r"(a[1]), "r"(a[2]), "r"(a[3]), "r"(b0), "r"(b1));
}

// ---------------- stage loader: A, B -> padded smem ----------------
__device__ __forceinline__ void load_stage(uint32_t sb,
    const __half* Ap, const __half* Bp, int K, int kt, int tid)
{
#pragma unroll
    for (int j = 0; j < 2; j++) {
        const int idx = tid + j * 256;            // 0..511
        const int row = idx >> 2, c = idx & 3;
        const size_t go = (size_t)row * K + kt + c * 8;
        const uint32_t so = row * KPAD_B + c * 16;
        cp16(sb + OFF_A + so, Ap + go);
        cp16(sb + OFF_B + so, Bp + go);
    }
}

// ---------------- tensor-core GEMM: D = alpha*A@B^T (+epilogue), fp16 ----------------
// EPI: 0 scale, 1 +res, 2 relu(+bias), 3 +bias+res
// MODE: 0 none, 1 causal (skip blocks above diagonal), 2 clamp K to (by+1)*BM,
//       3 symmetric (bx<=by only; mirror strict-lower elements)
// OUTB: 0 -> fp32 C; 1 -> fp16 Ch
template<int EPI, int MODE, int OUTB>
__global__ __launch_bounds__(GT, 1)
void gemm_mma(const __half* __restrict__ Ah, const __half* __restrict__ Bh,
              float* __restrict__ C, __half* __restrict__ Ch,
              const float* __restrict__ Rres, const float* __restrict__ bias,
              int M, int N, int K, float alpha,
              long long strideA, long long strideB, long long strideC)
{
    const int bx = blockIdx.x, by = blockIdx.y, bz = blockIdx.z;
    if ((MODE == 1 || MODE == 3) && bx > by) return;

    extern __shared__ char smem[];
    const uint32_t sb0 = smem_u32(smem);

    const int tid = threadIdx.x;
    const int wid = tid >> 5, lane = tid & 31;
    const int warp_m = wid >> 2, warp_n = wid & 3;   // 2 x 4 warps; warp tile 64m x 32n
    const int lrow16 = lane & 15, lhi = lane >> 4;
    const int gr = lane >> 2, tg = lane & 3;

    const __half* Ap = Ah + (size_t)bz * strideA + (size_t)by * BM * K;
    const __half* Bp = Bh + (size_t)bz * strideB + (size_t)bx * BN * K;

    int kEnd = K;
    if (MODE == 2) { int ke = (by + 1) * BM; kEnd = ke < K ? ke : K; }
    const int nch = kEnd / BK;

    float acc[4][4][4];
#pragma unroll
    for (int mf = 0; mf < 4; mf++)
#pragma unroll
        for (int nf = 0; nf < 4; nf++)
#pragma unroll
            for (int r = 0; r < 4; r++) acc[mf][nf][r] = 0.f;

    const uint32_t a_lane = (uint32_t)((warp_m * 64 + lrow16) * KPAD_B + lhi * 16);
    const uint32_t b_lane = (uint32_t)((warp_n * 32 + lrow16) * KPAD_B + lhi * 16);

    load_stage(sb0, Ap, Bp, K, 0, tid);
    cp_commit();

    for (int c = 0; c < nch; ++c) {
        if (c + 1 < nch) {
            load_stage(sb0 + ((c + 1) & 1) * STAGE_B, Ap, Bp, K, (c + 1) * BK, tid);
            cp_commit();
            asm volatile("cp.async.wait_group 1;" ::: "memory");
        } else {
            asm volatile("cp.async.wait_group 0;" ::: "memory");
        }
        __syncthreads();

        const uint32_t buf = sb0 + (c & 1) * STAGE_B;
#pragma unroll
        for (int ks = 0; ks < 2; ks++) {
            uint32_t a_h[4][4], b_h[2][4];
#pragma unroll
            for (int mf = 0; mf < 4; mf++) {
                const uint32_t ad = buf + a_lane + (uint32_t)(mf * 16 * KPAD_B + ks * 32);
                ldsm4(a_h[mf], ad + OFF_A);
            }
#pragma unroll
            for (int hN = 0; hN < 2; hN++) {
                const uint32_t bd = buf + b_lane + (uint32_t)(hN * 16 * KPAD_B + ks * 32);
                ldsm4(b_h[hN], bd + OFF_B);
            }
#pragma unroll
            for (int mf = 0; mf < 4; mf++) {
#pragma unroll
                for (int nf = 0; nf < 4; nf++) {
                    const uint32_t bh0 = b_h[nf >> 1][nf & 1], bh1 = b_h[nf >> 1][2 + (nf & 1)];
                    mma16816(acc[mf][nf], a_h[mf], bh0, bh1);
                }
            }
        }
        __syncthreads();
    }

    // ---------------- epilogue ----------------
#pragma unroll
    for (int mf = 0; mf < 4; mf++) {
#pragma unroll
        for (int nf = 0; nf < 4; nf++) {
#pragma unroll
            for (int half = 0; half < 2; half++) {
                const int row = by * BM + warp_m * 64 + mf * 16 + gr + half * 8;
                const int col = bx * BN + warp_n * 32 + nf * 8 + tg * 2;
                float v0 = acc[mf][nf][half * 2 + 0] * alpha;
                float v1 = acc[mf][nf][half * 2 + 1] * alpha;
                if (EPI == 2 || EPI == 3) {
                    const float2 bb = *reinterpret_cast<const float2*>(&bias[col]);
                    v0 += bb.x; v1 += bb.y;
                }
                const size_t o = (size_t)bz * strideC + (size_t)row * N + col;
                if (EPI == 1 || EPI == 3) {
                    const float2 rr = *reinterpret_cast<const float2*>(&Rres[o]);
                    v0 += rr.x; v1 += rr.y;
                }
                if (EPI == 2) { v0 = fmaxf(v0, 0.f); v1 = fmaxf(v1, 0.f); }
                if (OUTB == 0) {
                    float2 st; st.x = v0; st.y = v1;
                    *reinterpret_cast<float2*>(&C[o]) = st;
                    if (MODE == 3) {   // mirror strict-lower elements
                        const size_t ob = (size_t)bz * strideC;
                        if (col < row)     C[ob + (size_t)col * N + row] = v0;
                        if (col + 1 < row) C[ob + (size_t)(col + 1) * N + row] = v1;
                    }
                } else {
                    __half2 hv = __floats2half2_rn(v0, v1);
                    *reinterpret_cast<uint32_t*>(&Ch[o]) =
                        *reinterpret_cast<const uint32_t*>(&hv);
                }
            }
        }
    }
}

// ---------------- softmax: fp32 scores -> fp16 P ----------------
template<int CAUSAL>
__global__ void softmax_half_kernel(const float* __restrict__ Sc,
                                    __half* __restrict__ Ph)
{
    const int T = 256, NC = S_ / T;
    const int row = blockIdx.x, b = blockIdx.y, t = threadIdx.x;
    const float* rp = Sc + ((size_t)b * S_ + row) * S_;
    __half* hp = Ph + ((size_t)b * S_ + row) * S_;
    const int limit = CAUSAL ? row + 1 : S_;
    const int blockEnd = CAUSAL ? (((row >> 7) + 1) << 7) : S_;

    float v[NC];
#pragma unroll
    for (int c = 0; c < NC; c++) {
        int j = t + c * T;
        v[c] = (j < limit) ? rp[j] : -INFINITY;
    }
    float m = -INFINITY;
#pragma unroll
    for (int c = 0; c < NC; c++) m = fmaxf(m, v[c]);
#pragma unroll
    for (int o = 16; o > 0; o >>= 1) m = fmaxf(m, __shfl_xor_sync(0xffffffffu, m, o));
    __shared__ float sred[8];
    if ((t & 31) == 0) sred[t >> 5] = m;
    __syncthreads();
    m = sred[0];
#pragma unroll
    for (int w = 1; w < 8; w++) m = fmaxf(m, sred[w]);
    __syncthreads();

    float s = 0.f;
#pragma unroll
    for (int c = 0; c < NC; c++) { float e = __expf(v[c] - m); v[c] = e; s += e; }
#pragma unroll
    for (int o = 16; o > 0; o >>= 1) s += __shfl_xor_sync(0xffffffffu, s, o);
    if ((t & 31) == 0) sred[t >> 5] = s;
    __syncthreads();
    s = 0.f;
#pragma unroll
    for (int w = 0; w < 8; w++) s += sred[w];
    const float inv = 1.f / s;
#pragma unroll
    for (int c = 0; c < NC; c++) {
        int j = t + c * T;
        if (j < blockEnd) hp[j] = __float2half_rn(v[c] * inv);
    }
}

// ---------------- elementwise fp32 -> fp16 ----------------
__global__ void half_kernel(const float* __restrict__ X, __half* __restrict__ H)
{
    const size_t i = ((size_t)blockIdx.x * 256 + threadIdx.x) * 4;
    float4 v = *reinterpret_cast<const float4*>(X + i);
    __half2 a = __floats2half2_rn(v.x, v.y);
    __half2 b = __floats2half2_rn(v.z, v.w);
    uint2 hv;
    hv.x = *reinterpret_cast<const uint32_t*>(&a);
    hv.y = *reinterpret_cast<const uint32_t*>(&b);
    *reinterpret_cast<uint2*>(H + i) = hv;
}

// ---------------- transpose + to-fp16: fp32 [B,S,D] -> fp16 [B,D,S] ----------------
__global__ void transpose_half_kernel(const float* __restrict__ X, __half* __restrict__ Th)
{
    __shared__ float t[32][33];
    const int b = blockIdx.z;
    const int d0 = blockIdx.x * 32, s0 = blockIdx.y * 32;
    const float* Xp = X + (size_t)b * S_ * D_;
    for (int i = threadIdx.y; i < 32; i += 8)
        t[i][threadIdx.x] = Xp[(size_t)(s0 + i) * D_ + d0 + threadIdx.x];
    __syncthreads();
    for (int i = threadIdx.y; i < 32; i += 8) {
        size_t o = (size_t)b * D_ * S_ + (size_t)(d0 + i) * S_ + s0 + threadIdx.x;
        Th[o] = __float2half_rn(t[threadIdx.x][i]);
    }
}

// ---------------- joint LayerNorm over (S, D) per batch ----------------
__global__ void ln_reduce1_kernel(const float* __restrict__ X)
{
    const int b = blockIdx.y;
    const float* p = X + (size_t)b * S_ * D_;
    const size_t chunk = (size_t)S_ * D_ / 256;
    const size_t start = (size_t)blockIdx.x * chunk;
    double s = 0.0, s2 = 0.0;
    for (size_t i = start + threadIdx.x; i < start + chunk; i += 256) {
        float v = p[i];
        s += (double)v; s2 += (double)v * (double)v;
    }
    __shared__ double sh[256], sh2[256];
    sh[threadIdx.x] = s; sh2[threadIdx.x] = s2;
    __syncthreads();
    for (int o = 128; o > 0; o >>= 1) {
        if (threadIdx.x < o) {
            sh[threadIdx.x] += sh[threadIdx.x + o];
            sh2[threadIdx.x] += sh2[threadIdx.x + o];
        }
        __syncthreads();
    }
    if (threadIdx.x == 0) {
        g_part[((size_t)b * 256 + blockIdx.x) * 2]     = sh[0];
        g_part[((size_t)b * 256 + blockIdx.x) * 2 + 1] = sh2[0];
    }
}

__global__ void ln_reduce2_kernel()
{
    const int b = blockIdx.x;
    double s  = g_part[((size_t)b * 256 + threadIdx.x) * 2];
    double s2 = g_part[((size_t)b * 256 + threadIdx.x) * 2 + 1];
    __shared__ double sh[256], sh2[256];
    sh[threadIdx.x] = s; sh2[threadIdx.x] = s2;
    __syncthreads();
    for (int o = 128; o > 0; o >>= 1) {
        if (threadIdx.x < o) {
            sh[threadIdx.x] += sh[threadIdx.x + o];
            sh2[threadIdx.x] += sh2[threadIdx.x + o];
        }
        __syncthreads();
    }
    if (threadIdx.x == 0) {
        const double n = (double)S_ * (double)D_;
        double mu  = sh[0] / n;
        double var = sh2[0] / n - mu * mu;
        g_stats[b * 2]     = (float)mu;
        g_stats[b * 2 + 1] = (float)(1.0 / sqrt(var + (double)LN_EPS));
    }
}

__global__ void ln_apply_kernel(const float* __restrict__ X, const float* __restrict__ G,
                                const float* __restrict__ Be, float* __restrict__ Y)
{
    const size_t idx = (size_t)blockIdx.x * blockDim.x + threadIdx.x;
    const size_t sd = idx & ((size_t)S_ * D_ - 1);
    const int b = (int)(idx >> 21);
    const float mu = g_stats[b * 2], rs = g_stats[b * 2 + 1];
    Y[idx] = (X[idx] - mu) * rs * G[sd] + Be[sd];
}

__global__ void ln_apply_half_kernel(const float* __restrict__ X, const float* __restrict__ G,
                                     const float* __restrict__ Be, float* __restrict__ Y,
                                     __half* __restrict__ Yh)
{
    const size_t idx = (size_t)blockIdx.x * blockDim.x + threadIdx.x;
    const size_t sd = idx & ((size_t)S_ * D_ - 1);
    const int b = (int)(idx >> 21);
    const float mu = g_stats[b * 2], rs = g_stats[b * 2 + 1];
    float y = (X[idx] - mu) * rs * G[sd] + Be[sd];
    Y[idx] = y;
    Yh[idx] = __float2half_rn(y);
}

// ---------------- orchestration ----------------
extern "C" void kernel_launch(void* const* d_in, const int* in_sizes, int n_in,
                              void* d_out, int out_size)
{
    (void)in_sizes; (void)n_in; (void)out_size;
    const float* x    = (const float*)d_in[0];
    const float* enc  = (const float*)d_in[1];
    const float* Wo1  = (const float*)d_in[2];
    const float* Wo2  = (const float*)d_in[3];
    const float* ln1g = (const float*)d_in[4];
    const float* ln1b = (const float*)d_in[5];
    const float* ln2g = (const float*)d_in[6];
    const float* ln2b = (const float*)d_in[7];
    const float* W1   = (const float*)d_in[8];
    const float* b1   = (const float*)d_in[9];
    const float* W2   = (const float*)d_in[10];
    const float* b2   = (const float*)d_in[11];
    float* out = (float*)d_out;

    float *scores, *t2, *x1, *x2;
    cudaGetSymbolAddress((void**)&scores, g_scores);
    cudaGetSymbolAddress((void**)&t2, g_t2);
    cudaGetSymbolAddress((void**)&x1, g_x1);
    cudaGetSymbolAddress((void**)&x2, g_x2);
    __half *xh, *eh, *vth, *Ph, *t1h, *x2h, *hh;
    __half *wo1h, *wo2h, *w1h, *w2h;
    cudaGetSymbolAddress((void**)&xh, g_xh);
    cudaGetSymbolAddress((void**)&eh, g_eh);
    cudaGetSymbolAddress((void**)&vth, g_vth);
    cudaGetSymbolAddress((void**)&Ph, g_Ph);
    cudaGetSymbolAddress((void**)&t1h, g_t1h);
    cudaGetSymbolAddress((void**)&x2h, g_x2h);
    cudaGetSymbolAddress((void**)&hh, g_hh);
    cudaGetSymbolAddress((void**)&wo1h, g_wo1h); cudaGetSymbolAddress((void**)&wo2h, g_wo2h);
    cudaGetSymbolAddress((void**)&w1h, g_w1h);   cudaGetSymbolAddress((void**)&w2h, g_w2h);

    cudaFuncSetAttribute(gemm_mma<0,1,0>, cudaFuncAttributeMaxDynamicSharedMemorySize, SMEM_DYN);
    cudaFuncSetAttribute(gemm_mma<0,3,0>, cudaFuncAttributeMaxDynamicSharedMemorySize, SMEM_DYN);
    cudaFuncSetAttribute(gemm_mma<0,2,1>, cudaFuncAttributeMaxDynamicSharedMemorySize, SMEM_DYN);
    cudaFuncSetAttribute(gemm_mma<0,0,1>, cudaFuncAttributeMaxDynamicSharedMemorySize, SMEM_DYN);
    cudaFuncSetAttribute(gemm_mma<1,0,0>, cudaFuncAttributeMaxDynamicSharedMemorySize, SMEM_DYN);
    cudaFuncSetAttribute(gemm_mma<2,0,1>, cudaFuncAttributeMaxDynamicSharedMemorySize, SMEM_DYN);
    cudaFuncSetAttribute(gemm_mma<3,0,0>, cudaFuncAttributeMaxDynamicSharedMemorySize, SMEM_DYN);

    const dim3 blk(GT);
    const float scale = 1.0f / sqrtf((float)D_);
    const long long sSS = (long long)S_ * S_;
    const long long sSD = (long long)S_ * D_;
    const long long sDS = (long long)D_ * S_;
    const int lnBlocks = (B_ * S_ * D_) / 256;
    const size_t nBSD = (size_t)B_ * S_ * D_;

    // ---- operand conversions ----
    half_kernel<<<(int)(nBSD / 1024), blk>>>(x, xh);
    half_kernel<<<(int)(nBSD / 1024), blk>>>(enc, eh);
    half_kernel<<<D_ * D_ / 1024, blk>>>(Wo1, wo1h);
    half_kernel<<<D_ * D_ / 1024, blk>>>(Wo2, wo2h);
    half_kernel<<<F_ * D_ / 1024, blk>>>(W1, w1h);

    // ---- 1) causal self-attention + Wo1 + residual + ln1 ----
    gemm_mma<0,1,0><<<dim3(S_ / BN, S_ / BM, B_), blk, SMEM_DYN>>>(
        xh, xh, scores, nullptr, nullptr, nullptr,
        S_, S_, D_, scale, sSD, sSD, sSS);

    half_kernel<<<D_ * F_ / 1024, blk>>>(W2, w2h);
    transpose_half_kernel<<<dim3(D_ / 32, S_ / 32, B_), dim3(32, 8)>>>(x, vth);

    softmax_half_kernel<1><<<dim3(S_, B_), blk>>>(scores, Ph);
    gemm_mma<0,2,1><<<dim3(D_ / BN, S_ / BM, B_), blk, SMEM_DYN>>>(
        Ph, vth, nullptr, t1h, nullptr, nullptr,
        S_, D_, S_, 1.f, sSS, sDS, sSD);
    gemm_mma<1,0,0><<<dim3(D_ / BN, (B_ * S_) / BM, 1), blk, SMEM_DYN>>>(
        t1h, wo1h, t2, nullptr, x, nullptr,
        B_ * S_, D_, D_, 1.f, 0, 0, 0);
    ln_reduce1_kernel<<<dim3(256, B_), blk>>>(t2);
    ln_reduce2_kernel<<<B_, blk>>>();
    ln_apply_kernel<<<lnBlocks, blk>>>(t2, ln1g, ln1b, x1);
    transpose_half_kernel<<<dim3(D_ / 32, S_ / 32, B_), dim3(32, 8)>>>(x1, vth);

    // ---- 2) cross attention (q=k=enc, v=x1): scores symmetric -> half the blocks ----
    gemm_mma<0,3,0><<<dim3(S_ / BN, S_ / BM, B_), blk, SMEM_DYN>>>(
        eh, eh, scores, nullptr, nullptr, nullptr,
        S_, S_, D_, scale, sSD, sSD, sSS);
    softmax_half_kernel<0><<<dim3(S_, B_), blk>>>(scores, Ph);
    gemm_mma<0,0,1><<<dim3(D_ / BN, S_ / BM, B_), blk, SMEM_DYN>>>(
        Ph, vth, nullptr, t1h, nullptr, nullptr,
        S_, D_, S_, 1.f, sSS, sDS, sSD);
    gemm_mma<1,0,0><<<dim3(D_ / BN, (B_ * S_) / BM, 1), blk, SMEM_DYN>>>(
        t1h, wo2h, t2, nullptr, x1, nullptr,
        B_ * S_, D_, D_, 1.f, 0, 0, 0);
    ln_reduce1_kernel<<<dim3(256, B_), blk>>>(t2);
    ln_reduce2_kernel<<<B_, blk>>>();
    ln_apply_half_kernel<<<lnBlocks, blk>>>(t2, ln2g, ln2b, x2, x2h);

    // ---- 3) FFN + residual + ln2 (shared params) ----
    gemm_mma<2,0,1><<<dim3(F_ / BN, (B_ * S_) / BM, 1), blk, SMEM_DYN>>>(
        x2h, w1h, nullptr, hh, nullptr, b1,
        B_ * S_, F_, D_, 1.f, 0, 0, 0);
    gemm_mma<3,0,0><<<dim3(D_ / BN, (B_ * S_) / BM, 1), blk, SMEM_DYN>>>(
        hh, w2h, t2, nullptr, x2, b2,
        B_ * S_, D_, F_, 1.f, 0, 0, 0);
    ln_reduce1_kernel<<<dim3(256, B_), blk>>>(t2);
    ln_reduce2_kernel<<<B_, blk>>>();
    ln_apply_kernel<<<lnBlocks, blk>>>(t2, ln2g, ln2b, out);
}

// round 9
// speedup vs baseline: 2.2757x; 1.0574x over previous
#include <cuda_runtime.h>
#include <cuda_fp16.h>
#include <math.h>
#include <stdint.h>

#define B_ 4
#define S_ 4096
#define D_ 512
#define F_ 2048
#define LN_EPS 1e-5f

#define BM 128
#define BN 128
#define BK 32
#define GT 256
#define KPAD_B 80                      // 32 fp16 padded to 40 -> 80 bytes/row
#define TILE_B (128 * KPAD_B)          // 10240 B
#define OFF_A 0
#define OFF_B (TILE_B)
#define STAGE_B (2 * TILE_B)           // 20480
#define NSTAGE 3
#define SMEM_DYN (NSTAGE * STAGE_B)    // 61440

// ---------------- scratch ----------------
__device__ __align__(128) float g_scores[(size_t)B_ * S_ * S_];
__device__ __align__(128) float g_t2[(size_t)B_ * S_ * D_];
__device__ __align__(128) float g_x1[(size_t)B_ * S_ * D_];
__device__ __align__(128) float g_x2[(size_t)B_ * S_ * D_];
__device__ double g_part[(size_t)B_ * 256 * 2];
__device__ float g_stats[B_ * 2];

__device__ __align__(128) __half g_xh[(size_t)B_*S_*D_];
__device__ __align__(128) __half g_eh[(size_t)B_*S_*D_];
__device__ __align__(128) __half g_vth[(size_t)B_*D_*S_];
__device__ __align__(128) __half g_Ph[(size_t)B_*S_*S_];
__device__ __align__(128) __half g_t1h[(size_t)B_*S_*D_];
__device__ __align__(128) __half g_x2h[(size_t)B_*S_*D_];
__device__ __align__(128) __half g_hh[(size_t)B_*S_*F_];
__device__ __align__(128) __half g_wo1h[D_*D_], g_wo2h[D_*D_];
__device__ __align__(128) __half g_w1h[F_*D_],  g_w2h[D_*F_];

// ---------------- PTX helpers ----------------
__device__ __forceinline__ uint32_t smem_u32(const void* p) {
    return (uint32_t)__cvta_generic_to_shared(p);
}
__device__ __forceinline__ void cp16(uint32_t dst, const void* src) {
    asm volatile("cp.async.cg.shared.global [%0], [%1], 16;" :: "r"(dst), "l"(src));
}
__device__ __forceinline__ void cp_commit() {
    asm volatile("cp.async.commit_group;" ::: "memory");
}
__device__ __forceinline__ void ldsm4(uint32_t (&r)[4], uint32_t addr) {
    asm volatile("ldmatrix.sync.aligned.m8n8.x4.shared.b16 {%0,%1,%2,%3}, [%4];"
                 : "=r"(r[0]), "=r"(r[1]), "=r"(r[2]), "=r"(r[3]) : "r"(addr));
}
__device__ __forceinline__ void mma16816(float (&c)[4], const uint32_t (&a)[4],
                                         uint32_t b0, uint32_t b1) {
    asm volatile(
        "mma.sync.aligned.m16n8k16.row.col.f32.f16.f16.f32 "
        "{%0,%1,%2,%3}, {%4,%5,%6,%7}, {%8,%9}, {%0,%1,%2,%3};"
        : "+f"(c[0]), "+f"(c[1]), "+f"(c[2]), "+f"(c[3])
        : "r"(a[0]), "r"(a[1]), "r"(a[2]), "r"(a[3]), "r"(b0), "r"(b1));
}

// ---------------- stage loader: A, B -> padded smem ----------------
__device__ __forceinline__ void load_stage(uint32_t sb,
    const __half* Ap, const __half* Bp, int K, int kt, int tid)
{
#pragma unroll
    for (int j = 0; j < 2; j++) {
        const int idx = tid + j * 256;            // 0..511
        const int row = idx >> 2, c = idx & 3;
        const size_t go = (size_t)row * K + kt + c * 8;
        const uint32_t so = row * KPAD_B + c * 16;
        cp16(sb + OFF_A + so, Ap + go);
        cp16(sb + OFF_B + so, Bp + go);
    }
}

// ---------------- tensor-core GEMM: D = alpha*A@B^T (+epilogue), fp16 ----------------
// EPI: 0 scale, 1 +res, 2 relu(+bias), 3 +bias+res
// MODE: 0 none, 1 causal (skip blocks above diagonal), 2 clamp K to (by+1)*BM,
//       3 symmetric (bx<=by only; mirror strict-lower elements)
// OUTB: 0 -> fp32 C; 1 -> fp16 Ch
template<int EPI, int MODE, int OUTB>
__global__ __launch_bounds__(GT, 2)
void gemm_mma(const __half* __restrict__ Ah, const __half* __restrict__ Bh,
              float* __restrict__ C, __half* __restrict__ Ch,
              const float* __restrict__ Rres, const float* __restrict__ bias,
              int M, int N, int K, float alpha,
              long long strideA, long long strideB, long long strideC)
{
    const int bx = blockIdx.x, by = blockIdx.y, bz = blockIdx.z;
    if ((MODE == 1 || MODE == 3) && bx > by) return;

    extern __shared__ char smem[];
    const uint32_t sb0 = smem_u32(smem);

    const int tid = threadIdx.x;
    const int wid = tid >> 5, lane = tid & 31;
    const int warp_m = wid >> 2, warp_n = wid & 3;   // 2 x 4 warps; warp tile 64m x 32n
    const int lrow16 = lane & 15, lhi = lane >> 4;
    const int gr = lane >> 2, tg = lane & 3;

    const __half* Ap = Ah + (size_t)bz * strideA + (size_t)by * BM * K;
    const __half* Bp = Bh + (size_t)bz * strideB + (size_t)bx * BN * K;

    int kEnd = K;
    if (MODE == 2) { int ke = (by + 1) * BM; kEnd = ke < K ? ke : K; }
    const int nch = kEnd / BK;

    float acc[4][4][4];
#pragma unroll
    for (int mf = 0; mf < 4; mf++)
#pragma unroll
        for (int nf = 0; nf < 4; nf++)
#pragma unroll
            for (int r = 0; r < 4; r++) acc[mf][nf][r] = 0.f;

    const uint32_t a_lane = (uint32_t)((warp_m * 64 + lrow16) * KPAD_B + lhi * 16);
    const uint32_t b_lane = (uint32_t)((warp_n * 32 + lrow16) * KPAD_B + lhi * 16);

    // 3-stage prologue: stages 0 and 1 in flight
    load_stage(sb0, Ap, Bp, K, 0, tid);
    cp_commit();
    if (nch > 1) {
        load_stage(sb0 + STAGE_B, Ap, Bp, K, BK, tid);
        cp_commit();
    }

    int sidx = 0;
    for (int c = 0; c < nch; ++c) {
        if (c + 1 < nch) {
            asm volatile("cp.async.wait_group 1;" ::: "memory");   // stage c ready
        } else {
            asm volatile("cp.async.wait_group 0;" ::: "memory");
        }
        __syncthreads();   // also proves all warps finished compute(c-1) -> stage (c+2)%3 free
        if (c + 2 < nch) {
            int ls = sidx + 2; if (ls >= NSTAGE) ls -= NSTAGE;
            load_stage(sb0 + ls * STAGE_B, Ap, Bp, K, (c + 2) * BK, tid);
            cp_commit();
        }

        const uint32_t buf = sb0 + sidx * STAGE_B;
#pragma unroll
        for (int ks = 0; ks < 2; ks++) {
            uint32_t a_h[4][4], b_h[2][4];
#pragma unroll
            for (int mf = 0; mf < 4; mf++) {
                const uint32_t ad = buf + a_lane + (uint32_t)(mf * 16 * KPAD_B + ks * 32);
                ldsm4(a_h[mf], ad + OFF_A);
            }
#pragma unroll
            for (int hN = 0; hN < 2; hN++) {
                const uint32_t bd = buf + b_lane + (uint32_t)(hN * 16 * KPAD_B + ks * 32);
                ldsm4(b_h[hN], bd + OFF_B);
            }
#pragma unroll
            for (int mf = 0; mf < 4; mf++) {
#pragma unroll
                for (int nf = 0; nf < 4; nf++) {
                    const uint32_t bh0 = b_h[nf >> 1][nf & 1], bh1 = b_h[nf >> 1][2 + (nf & 1)];
                    mma16816(acc[mf][nf], a_h[mf], bh0, bh1);
                }
            }
        }
        sidx++; if (sidx == NSTAGE) sidx = 0;
    }

    // ---------------- epilogue ----------------
#pragma unroll
    for (int mf = 0; mf < 4; mf++) {
#pragma unroll
        for (int nf = 0; nf < 4; nf++) {
#pragma unroll
            for (int half = 0; half < 2; half++) {
                const int row = by * BM + warp_m * 64 + mf * 16 + gr + half * 8;
                const int col = bx * BN + warp_n * 32 + nf * 8 + tg * 2;
                float v0 = acc[mf][nf][half * 2 + 0] * alpha;
                float v1 = acc[mf][nf][half * 2 + 1] * alpha;
                if (EPI == 2 || EPI == 3) {
                    const float2 bb = *reinterpret_cast<const float2*>(&bias[col]);
                    v0 += bb.x; v1 += bb.y;
                }
                const size_t o = (size_t)bz * strideC + (size_t)row * N + col;
                if (EPI == 1 || EPI == 3) {
                    const float2 rr = *reinterpret_cast<const float2*>(&Rres[o]);
                    v0 += rr.x; v1 += rr.y;
                }
                if (EPI == 2) { v0 = fmaxf(v0, 0.f); v1 = fmaxf(v1, 0.f); }
                if (OUTB == 0) {
                    float2 st; st.x = v0; st.y = v1;
                    *reinterpret_cast<float2*>(&C[o]) = st;
                    if (MODE == 3) {   // mirror strict-lower elements
                        const size_t ob = (size_t)bz * strideC;
                        if (col < row)     C[ob + (size_t)col * N + row] = v0;
                        if (col + 1 < row) C[ob + (size_t)(col + 1) * N + row] = v1;
                    }
                } else {
                    __half2 hv = __floats2half2_rn(v0, v1);
                    *reinterpret_cast<uint32_t*>(&Ch[o]) =
                        *reinterpret_cast<const uint32_t*>(&hv);
                }
            }
        }
    }
}

// ---------------- softmax: fp32 scores -> fp16 P ----------------
template<int CAUSAL>
__global__ void softmax_half_kernel(const float* __restrict__ Sc,
                                    __half* __restrict__ Ph)
{
    const int T = 256, NC = S_ / T;
    const int row = blockIdx.x, b = blockIdx.y, t = threadIdx.x;
    const float* rp = Sc + ((size_t)b * S_ + row) * S_;
    __half* hp = Ph + ((size_t)b * S_ + row) * S_;
    const int limit = CAUSAL ? row + 1 : S_;
    const int blockEnd = CAUSAL ? (((row >> 7) + 1) << 7) : S_;

    float v[NC];
#pragma unroll
    for (int c = 0; c < NC; c++) {
        int j = t + c * T;
        v[c] = (j < limit) ? rp[j] : -INFINITY;
    }
    float m = -INFINITY;
#pragma unroll
    for (int c = 0; c < NC; c++) m = fmaxf(m, v[c]);
#pragma unroll
    for (int o = 16; o > 0; o >>= 1) m = fmaxf(m, __shfl_xor_sync(0xffffffffu, m, o));
    __shared__ float sred[8];
    if ((t & 31) == 0) sred[t >> 5] = m;
    __syncthreads();
    m = sred[0];
#pragma unroll
    for (int w = 1; w < 8; w++) m = fmaxf(m, sred[w]);
    __syncthreads();

    float s = 0.f;
#pragma unroll
    for (int c = 0; c < NC; c++) { float e = __expf(v[c] - m); v[c] = e; s += e; }
#pragma unroll
    for (int o = 16; o > 0; o >>= 1) s += __shfl_xor_sync(0xffffffffu, s, o);
    if ((t & 31) == 0) sred[t >> 5] = s;
    __syncthreads();
    s = 0.f;
#pragma unroll
    for (int w = 0; w < 8; w++) s += sred[w];
    const float inv = 1.f / s;
#pragma unroll
    for (int c = 0; c < NC; c++) {
        int j = t + c * T;
        if (j < blockEnd) hp[j] = __float2half_rn(v[c] * inv);
    }
}

// ---------------- elementwise fp32 -> fp16 ----------------
__global__ void half_kernel(const float* __restrict__ X, __half* __restrict__ H)
{
    const size_t i = ((size_t)blockIdx.x * 256 + threadIdx.x) * 4;
    float4 v = *reinterpret_cast<const float4*>(X + i);
    __half2 a = __floats2half2_rn(v.x, v.y);
    __half2 b = __floats2half2_rn(v.z, v.w);
    uint2 hv;
    hv.x = *reinterpret_cast<const uint32_t*>(&a);
    hv.y = *reinterpret_cast<const uint32_t*>(&b);
    *reinterpret_cast<uint2*>(H + i) = hv;
}

// ---------------- fused: fp32 [B,S,D] -> fp16 row-major + fp16 transposed ----------------
__global__ void conv_half_tr_kernel(const float* __restrict__ X,
                                    __half* __restrict__ H, __half* __restrict__ Th)
{
    __shared__ float t[32][33];
    const int b = blockIdx.z;
    const int d0 = blockIdx.x * 32, s0 = blockIdx.y * 32;
    const float* Xp = X + (size_t)b * S_ * D_;
    __half* Hp = H + (size_t)b * S_ * D_;
    for (int i = threadIdx.y; i < 32; i += 8) {
        const size_t sd = (size_t)(s0 + i) * D_ + d0 + threadIdx.x;
        float v = Xp[sd];
        t[i][threadIdx.x] = v;
        Hp[sd] = __float2half_rn(v);
    }
    __syncthreads();
    for (int i = threadIdx.y; i < 32; i += 8) {
        size_t o = (size_t)b * D_ * S_ + (size_t)(d0 + i) * S_ + s0 + threadIdx.x;
        Th[o] = __float2half_rn(t[threadIdx.x][i]);
    }
}

// ---------------- fused: LN-apply + fp32 out + fp16 transposed out ----------------
__global__ void ln_apply_tr_kernel(const float* __restrict__ X, const float* __restrict__ G,
                                   const float* __restrict__ Be,
                                   float* __restrict__ Y, __half* __restrict__ Th)
{
    __shared__ float t[32][33];
    const int b = blockIdx.z;
    const int d0 = blockIdx.x * 32, s0 = blockIdx.y * 32;
    const float mu = g_stats[b * 2], rs = g_stats[b * 2 + 1];
    const float* Xp = X + (size_t)b * S_ * D_;
    float* Yp = Y + (size_t)b * S_ * D_;
    for (int i = threadIdx.y; i < 32; i += 8) {
        const size_t sd = (size_t)(s0 + i) * D_ + d0 + threadIdx.x;
        float y = (Xp[sd] - mu) * rs * G[sd] + Be[sd];
        t[i][threadIdx.x] = y;
        Yp[sd] = y;
    }
    __syncthreads();
    for (int i = threadIdx.y; i < 32; i += 8) {
        size_t o = (size_t)b * D_ * S_ + (size_t)(d0 + i) * S_ + s0 + threadIdx.x;
        Th[o] = __float2half_rn(t[threadIdx.x][i]);
    }
}

// ---------------- joint LayerNorm over (S, D) per batch ----------------
__global__ void ln_reduce1_kernel(const float* __restrict__ X)
{
    const int b = blockIdx.y;
    const float* p = X + (size_t)b * S_ * D_;
    const size_t chunk = (size_t)S_ * D_ / 256;
    const size_t start = (size_t)blockIdx.x * chunk;
    double s = 0.0, s2 = 0.0;
    for (size_t i = start + threadIdx.x; i < start + chunk; i += 256) {
        float v = p[i];
        s += (double)v; s2 += (double)v * (double)v;
    }
    __shared__ double sh[256], sh2[256];
    sh[threadIdx.x] = s; sh2[threadIdx.x] = s2;
    __syncthreads();
    for (int o = 128; o > 0; o >>= 1) {
        if (threadIdx.x < o) {
            sh[threadIdx.x] += sh[threadIdx.x + o];
            sh2[threadIdx.x] += sh2[threadIdx.x + o];
        }
        __syncthreads();
    }
    if (threadIdx.x == 0) {
        g_part[((size_t)b * 256 + blockIdx.x) * 2]     = sh[0];
        g_part[((size_t)b * 256 + blockIdx.x) * 2 + 1] = sh2[0];
    }
}

__global__ void ln_reduce2_kernel()
{
    const int b = blockIdx.x;
    double s  = g_part[((size_t)b * 256 + threadIdx.x) * 2];
    double s2 = g_part[((size_t)b * 256 + threadIdx.x) * 2 + 1];
    __shared__ double sh[256], sh2[256];
    sh[threadIdx.x] = s; sh2[threadIdx.x] = s2;
    __syncthreads();
    for (int o = 128; o > 0; o >>= 1) {
        if (threadIdx.x < o) {
            sh[threadIdx.x] += sh[threadIdx.x + o];
            sh2[threadIdx.x] += sh2[threadIdx.x + o];
        }
        __syncthreads();
    }
    if (threadIdx.x == 0) {
        const double n = (double)S_ * (double)D_;
        double mu  = sh[0] / n;
        double var = sh2[0] / n - mu * mu;
        g_stats[b * 2]     = (float)mu;
        g_stats[b * 2 + 1] = (float)(1.0 / sqrt(var + (double)LN_EPS));
    }
}

__global__ void ln_apply_kernel(const float* __restrict__ X, const float* __restrict__ G,
                                const float* __restrict__ Be, float* __restrict__ Y)
{
    const size_t idx = (size_t)blockIdx.x * blockDim.x + threadIdx.x;
    const size_t sd = idx & ((size_t)S_ * D_ - 1);
    const int b = (int)(idx >> 21);
    const float mu = g_stats[b * 2], rs = g_stats[b * 2 + 1];
    Y[idx] = (X[idx] - mu) * rs * G[sd] + Be[sd];
}

__global__ void ln_apply_half_kernel(const float* __restrict__ X, const float* __restrict__ G,
                                     const float* __restrict__ Be, float* __restrict__ Y,
                                     __half* __restrict__ Yh)
{
    const size_t idx = (size_t)blockIdx.x * blockDim.x + threadIdx.x;
    const size_t sd = idx & ((size_t)S_ * D_ - 1);
    const int b = (int)(idx >> 21);
    const float mu = g_stats[b * 2], rs = g_stats[b * 2 + 1];
    float y = (X[idx] - mu) * rs * G[sd] + Be[sd];
    Y[idx] = y;
    Yh[idx] = __float2half_rn(y);
}

// ---------------- orchestration ----------------
extern "C" void kernel_launch(void* const* d_in, const int* in_sizes, int n_in,
                              void* d_out, int out_size)
{
    (void)in_sizes; (void)n_in; (void)out_size;
    const float* x    = (const float*)d_in[0];
    const float* enc  = (const float*)d_in[1];
    const float* Wo1  = (const float*)d_in[2];
    const float* Wo2  = (const float*)d_in[3];
    const float* ln1g = (const float*)d_in[4];
    const float* ln1b = (const float*)d_in[5];
    const float* ln2g = (const float*)d_in[6];
    const float* ln2b = (const float*)d_in[7];
    const float* W1   = (const float*)d_in[8];
    const float* b1   = (const float*)d_in[9];
    const float* W2   = (const float*)d_in[10];
    const float* b2   = (const float*)d_in[11];
    float* out = (float*)d_out;

    float *scores, *t2, *x1, *x2;
    cudaGetSymbolAddress((void**)&scores, g_scores);
    cudaGetSymbolAddress((void**)&t2, g_t2);
    cudaGetSymbolAddress((void**)&x1, g_x1);
    cudaGetSymbolAddress((void**)&x2, g_x2);
    __half *xh, *eh, *vth, *Ph, *t1h, *x2h, *hh;
    __half *wo1h, *wo2h, *w1h, *w2h;
    cudaGetSymbolAddress((void**)&xh, g_xh);
    cudaGetSymbolAddress((void**)&eh, g_eh);
    cudaGetSymbolAddress((void**)&vth, g_vth);
    cudaGetSymbolAddress((void**)&Ph, g_Ph);
    cudaGetSymbolAddress((void**)&t1h, g_t1h);
    cudaGetSymbolAddress((void**)&x2h, g_x2h);
    cudaGetSymbolAddress((void**)&hh, g_hh);
    cudaGetSymbolAddress((void**)&wo1h, g_wo1h); cudaGetSymbolAddress((void**)&wo2h, g_wo2h);
    cudaGetSymbolAddress((void**)&w1h, g_w1h);   cudaGetSymbolAddress((void**)&w2h, g_w2h);

    cudaFuncSetAttribute(gemm_mma<0,1,0>, cudaFuncAttributeMaxDynamicSharedMemorySize, SMEM_DYN);
    cudaFuncSetAttribute(gemm_mma<0,3,0>, cudaFuncAttributeMaxDynamicSharedMemorySize, SMEM_DYN);
    cudaFuncSetAttribute(gemm_mma<0,2,1>, cudaFuncAttributeMaxDynamicSharedMemorySize, SMEM_DYN);
    cudaFuncSetAttribute(gemm_mma<0,0,1>, cudaFuncAttributeMaxDynamicSharedMemorySize, SMEM_DYN);
    cudaFuncSetAttribute(gemm_mma<1,0,0>, cudaFuncAttributeMaxDynamicSharedMemorySize, SMEM_DYN);
    cudaFuncSetAttribute(gemm_mma<2,0,1>, cudaFuncAttributeMaxDynamicSharedMemorySize, SMEM_DYN);
    cudaFuncSetAttribute(gemm_mma<3,0,0>, cudaFuncAttributeMaxDynamicSharedMemorySize, SMEM_DYN);

    const dim3 blk(GT);
    const float scale = 1.0f / sqrtf((float)D_);
    const long long sSS = (long long)S_ * S_;
    const long long sSD = (long long)S_ * D_;
    const long long sDS = (long long)D_ * S_;
    const int lnBlocks = (B_ * S_ * D_) / 256;
    const size_t nBSD = (size_t)B_ * S_ * D_;

    // ---- operand conversions ----
    conv_half_tr_kernel<<<dim3(D_ / 32, S_ / 32, B_), dim3(32, 8)>>>(x, xh, vth);
    half_kernel<<<(int)(nBSD / 1024), blk>>>(enc, eh);
    half_kernel<<<D_ * D_ / 1024, blk>>>(Wo1, wo1h);
    half_kernel<<<D_ * D_ / 1024, blk>>>(Wo2, wo2h);
    half_kernel<<<F_ * D_ / 1024, blk>>>(W1, w1h);
    half_kernel<<<D_ * F_ / 1024, blk>>>(W2, w2h);

    // ---- 1) causal self-attention + Wo1 + residual + ln1 ----
    gemm_mma<0,1,0><<<dim3(S_ / BN, S_ / BM, B_), blk, SMEM_DYN>>>(
        xh, xh, scores, nullptr, nullptr, nullptr,
        S_, S_, D_, scale, sSD, sSD, sSS);
    softmax_half_kernel<1><<<dim3(S_, B_), blk>>>(scores, Ph);
    gemm_mma<0,2,1><<<dim3(D_ / BN, S_ / BM, B_), blk, SMEM_DYN>>>(
        Ph, vth, nullptr, t1h, nullptr, nullptr,
        S_, D_, S_, 1.f, sSS, sDS, sSD);
    gemm_mma<1,0,0><<<dim3(D_ / BN, (B_ * S_) / BM, 1), blk, SMEM_DYN>>>(
        t1h, wo1h, t2, nullptr, x, nullptr,
        B_ * S_, D_, D_, 1.f, 0, 0, 0);
    ln_reduce1_kernel<<<dim3(256, B_), blk>>>(t2);
    ln_reduce2_kernel<<<B_, blk>>>();
    ln_apply_tr_kernel<<<dim3(D_ / 32, S_ / 32, B_), dim3(32, 8)>>>(t2, ln1g, ln1b, x1, vth);

    // ---- 2) cross attention (q=k=enc, v=x1): scores symmetric -> half the blocks ----
    gemm_mma<0,3,0><<<dim3(S_ / BN, S_ / BM, B_), blk, SMEM_DYN>>>(
        eh, eh, scores, nullptr, nullptr, nullptr,
        S_, S_, D_, scale, sSD, sSD, sSS);
    softmax_half_kernel<0><<<dim3(S_, B_), blk>>>(scores, Ph);
    gemm_mma<0,0,1><<<dim3(D_ / BN, S_ / BM, B_), blk, SMEM_DYN>>>(
        Ph, vth, nullptr, t1h, nullptr, nullptr,
        S_, D_, S_, 1.f, sSS, sDS, sSD);
    gemm_mma<1,0,0><<<dim3(D_ / BN, (B_ * S_) / BM, 1), blk, SMEM_DYN>>>(
        t1h, wo2h, t2, nullptr, x1, nullptr,
        B_ * S_, D_, D_, 1.f, 0, 0, 0);
    ln_reduce1_kernel<<<dim3(256, B_), blk>>>(t2);
    ln_reduce2_kernel<<<B_, blk>>>();
    ln_apply_half_kernel<<<lnBlocks, blk>>>(t2, ln2g, ln2b, x2, x2h);

    // ---- 3) FFN + residual + ln2 (shared params) ----
    gemm_mma<2,0,1><<<dim3(F_ / BN, (B_ * S_) / BM, 1), blk, SMEM_DYN>>>(
        x2h, w1h, nullptr, hh, nullptr, b1,
        B_ * S_, F_, D_, 1.f, 0, 0, 0);
    gemm_mma<3,0,0><<<dim3(D_ / BN, (B_ * S_) / BM, 1), blk, SMEM_DYN>>>(
        hh, w2h, t2, nullptr, x2, b2,
        B_ * S_, D_, F_, 1.f, 0, 0, 0);
    ln_reduce1_kernel<<<dim3(256, B_), blk>>>(t2);
    ln_reduce2_kernel<<<B_, blk>>>();
    ln_apply_kernel<<<lnBlocks, blk>>>(t2, ln2g, ln2b, out);
}